// round 1
// baseline (speedup 1.0000x reference)
#include <cuda_runtime.h>

#define NN 14      // nodes per graph
#define NH 4       // heads
#define NC 64      // per-head channels
#define NO 256     // NH*NC
#define FIN 128
#define NEG 0.2f
#define MAXE 256   // >= E + NN = 196

__device__ float g_wfused[NN*NC];   // W_lin @ W_pred  [896]
__device__ float g_bfused;
__device__ int   g_is64;

// Precompute fused head weights + detect edge dtype (int64 vs int32).
__global__ void prep_kernel(const float* __restrict__ Wlin, const float* __restrict__ blin,
                            const float* __restrict__ Wpred, const float* __restrict__ bpred,
                            const int* __restrict__ edges)
{
    int i = blockIdx.x * blockDim.x + threadIdx.x;
    if (i < NN*NC) {
        float s = 0.f;
        #pragma unroll
        for (int j = 0; j < NC/2; j++) s = fmaf(Wlin[i*(NC/2)+j], Wpred[j], s);
        g_wfused[i] = s;
    }
    if (i == 0) {
        float s = bpred[0];
        #pragma unroll
        for (int j = 0; j < NC/2; j++) s = fmaf(blin[j], Wpred[j], s);
        g_bfused = s;
        // int64 little-endian small values: every odd 32-bit word is 0.
        int any = 0;
        #pragma unroll
        for (int k = 1; k < 256; k += 2) any |= edges[k];
        g_is64 = (any == 0) ? 1 : 0;
    }
}

// One GAT layer entirely in shared memory.
// xs: input [NN, K] (row-major, 16B aligned). Output (head-mean + bias (+relu))
// overwrites xs[0 .. NN*NC).
template<int K, bool RELU>
__device__ __forceinline__ void gat_layer(
    const float* __restrict__ W, const float* __restrict__ a_s,
    const float* __restrict__ a_d, const float* __restrict__ bias,
    float* xs, float* hs, float* os, float* exs,
    float* den, float* alsrc, float* aldst,
    const int* srcS, const int* dstS, const int* off,
    int NE, int t, int lane, int h)
{
    // ---- GEMM: hs[n][t] = sum_k xs[n][k] * W[k][t] ----
    float acc[NN];
    #pragma unroll
    for (int n = 0; n < NN; n++) acc[n] = 0.f;

    const float4* x4 = (const float4*)xs;
    const float*  wp = W + t;
    #pragma unroll 2
    for (int k = 0; k < K; k += 4) {
        float w0 = wp[(k+0)*NO];
        float w1 = wp[(k+1)*NO];
        float w2 = wp[(k+2)*NO];
        float w3 = wp[(k+3)*NO];
        #pragma unroll
        for (int n = 0; n < NN; n++) {
            float4 xv = x4[n*(K/4) + (k >> 2)];
            float a = acc[n];
            a = fmaf(xv.x, w0, a);
            a = fmaf(xv.y, w1, a);
            a = fmaf(xv.z, w2, a);
            a = fmaf(xv.w, w3, a);
            acc[n] = a;
        }
    }

    // ---- epilogue: store h, reduce attention logits al_src/al_dst ----
    float av_s = a_s[t], av_d = a_d[t];
    #pragma unroll
    for (int n = 0; n < NN; n++) {
        hs[n*NO + t] = acc[n];
        float ps = acc[n] * av_s;
        float pd = acc[n] * av_d;
        #pragma unroll
        for (int o = 16; o; o >>= 1) {
            ps += __shfl_xor_sync(0xffffffffu, ps, o);
            pd += __shfl_xor_sync(0xffffffffu, pd, o);
        }
        if (lane == 0) {
            atomicAdd(&alsrc[n*NH + h], ps);
            atomicAdd(&aldst[n*NH + h], pd);
        }
    }
    __syncthreads();

    // ---- edge scores: leaky-relu + exp, denominator per (dst, head) ----
    for (int i = t; i < NE*NH; i += 256) {
        int e = i >> 2, hh = i & 3;
        float v = alsrc[srcS[e]*NH + hh] + aldst[dstS[e]*NH + hh];
        v = (v > 0.f) ? v : NEG * v;
        float ex = expf(v);
        exs[i] = ex;
        atomicAdd(&den[dstS[e]*NH + hh], ex);
    }
    __syncthreads();

    // ---- aggregation (edges sorted by dst -> register accumulation) ----
    #pragma unroll
    for (int n = 0; n < NN; n++) {
        float a = 0.f;
        int e1 = off[n+1];
        for (int e = off[n]; e < e1; e++)
            a = fmaf(exs[e*NH + h], hs[srcS[e]*NO + t], a);
        os[n*NO + t] = a / den[n*NH + h];
    }
    __syncthreads();

    // ---- head mean + bias (+relu) -> xs[0 .. NN*NC) ----
    for (int i = t; i < NN*NC; i += 256) {
        int n = i >> 6, c = i & 63;
        float v = 0.25f * (os[n*NO + c] + os[n*NO + c + 64]
                         + os[n*NO + c + 128] + os[n*NO + c + 192]) + bias[c];
        if (RELU) v = fmaxf(v, 0.f);
        xs[i] = v;
    }
    // re-zero reductions for the next layer
    if (t < NN*NH) { den[t] = 0.f; alsrc[t] = 0.f; aldst[t] = 0.f; }
    __syncthreads();
}

__global__ __launch_bounds__(256, 4)
void gat_kernel(const float* __restrict__ feature, const int* __restrict__ eraw,
                const float* __restrict__ W1, const float* __restrict__ as1,
                const float* __restrict__ ad1, const float* __restrict__ b1,
                const float* __restrict__ W2, const float* __restrict__ as2,
                const float* __restrict__ ad2, const float* __restrict__ b2,
                float* __restrict__ out, int E)
{
    __shared__ __align__(16) float xs[NN*FIN];     // features / layer inputs / final agg
    __shared__ float hs[NN*NO];                    // per-head GEMM output
    __shared__ float os[NN*NO];                    // aggregated output (pre head-mean)
    __shared__ float exs[MAXE*NH];                 // exp(edge score)
    __shared__ float den[NN*NH], alsrc[NN*NH], aldst[NN*NH];
    __shared__ int   srcS[MAXE], dstS[MAXE];
    __shared__ int   cnt[NN], off[NN+1];
    __shared__ float red[8];

    const int b = blockIdx.x, t = threadIdx.x;
    const int lane = t & 31, warp = t >> 5, h = t >> 6;
    const int NE = E + NN;
    const int is64 = g_is64;

    if (t < NN) cnt[t] = 0;
    if (t < NN*NH) { den[t] = 0.f; alsrc[t] = 0.f; aldst[t] = 0.f; }

    // load features [NN, FIN]
    const float* xg = feature + (size_t)b * NN * FIN;
    for (int i = t; i < NN*FIN; i += 256) xs[i] = xg[i];
    __syncthreads();

    // ---- counting sort of edges (incl. self-loops) by dst ----
    for (int e = t; e < NE; e += 256) {
        int d;
        if (e < E) {
            size_t base = ((size_t)b * E + e) * 2;
            d = is64 ? (int)((const long long*)eraw)[base + 1] : eraw[base + 1];
        } else d = e - E;
        atomicAdd(&cnt[d], 1);
    }
    __syncthreads();
    if (t == 0) {
        int s = 0;
        #pragma unroll
        for (int i = 0; i < NN; i++) { off[i] = s; s += cnt[i]; cnt[i] = off[i]; }
        off[NN] = s;
    }
    __syncthreads();
    for (int e = t; e < NE; e += 256) {
        int s, d;
        if (e < E) {
            size_t base = ((size_t)b * E + e) * 2;
            if (is64) { const long long* p = (const long long*)eraw;
                        s = (int)p[base]; d = (int)p[base + 1]; }
            else      { s = eraw[base];   d = eraw[base + 1]; }
        } else { s = d = e - E; }
        int pos = atomicAdd(&cnt[d], 1);
        srcS[pos] = s; dstS[pos] = d;
    }
    __syncthreads();

    gat_layer<FIN, true >(W1, as1, ad1, b1, xs, hs, os, exs, den, alsrc, aldst,
                          srcS, dstS, off, NE, t, lane, h);
    gat_layer<NC,  false>(W2, as2, ad2, b2, xs, hs, os, exs, den, alsrc, aldst,
                          srcS, dstS, off, NE, t, lane, h);

    // ---- fused head: p = agg2_flat . w_fused ; sigmoid ----
    float p = 0.f;
    for (int i = t; i < NN*NC; i += 256) p = fmaf(xs[i], g_wfused[i], p);
    #pragma unroll
    for (int o = 16; o; o >>= 1) p += __shfl_xor_sync(0xffffffffu, p, o);
    if (lane == 0) red[warp] = p;
    __syncthreads();
    if (t == 0) {
        float s = g_bfused;
        #pragma unroll
        for (int w = 0; w < 8; w++) s += red[w];
        out[b] = 1.f / (1.f + expf(-s));
    }
}

extern "C" void kernel_launch(void* const* d_in, const int* in_sizes, int n_in,
                              void* d_out, int out_size)
{
    const float* feature = (const float*)d_in[0];
    const int*   edges   = (const int*)  d_in[1];
    const float* W1   = (const float*)d_in[2];
    const float* as1  = (const float*)d_in[3];
    const float* ad1  = (const float*)d_in[4];
    const float* b1   = (const float*)d_in[5];
    const float* W2   = (const float*)d_in[6];
    const float* as2  = (const float*)d_in[7];
    const float* ad2  = (const float*)d_in[8];
    const float* b2   = (const float*)d_in[9];
    const float* Wlin = (const float*)d_in[10];
    const float* blin = (const float*)d_in[11];
    const float* Wpred= (const float*)d_in[12];
    const float* bpred= (const float*)d_in[13];

    int B = in_sizes[0] / (NN * FIN);       // 16384
    int E = in_sizes[1] / (2 * B);          // 182

    prep_kernel<<<4, 256>>>(Wlin, blin, Wpred, bpred, edges);
    gat_kernel<<<B, 256>>>(feature, edges, W1, as1, ad1, b1,
                           W2, as2, ad2, b2, (float*)d_out, E);
}

// round 2
// speedup vs baseline: 1.2488x; 1.2488x over previous
#include <cuda_runtime.h>

#define NN 14      // nodes per graph
#define NH 4       // heads
#define NC 64      // per-head channels
#define NO 256     // NH*NC
#define FIN 128
#define NEG 0.2f
#define MAXE 256   // >= E + NN = 196

// ---- precomputed weights (device globals, filled by prep_kernel) ----
__device__ float4 g_Wi1[32 * 256];    // W1 interleaved: [ks][c] = W1[4ks..4ks+3][c]
__device__ float4 g_Wi2[16 * 256];    // W2 interleaved
__device__ float  g_waSD1[8 * 128];   // [j][k]: j=0..3 -> W1[:,h]@a_src1[h], j=4..7 -> a_dst1
__device__ float  g_waSD2[8 * 64];
__device__ float  g_wfused[NN * NC];  // W_lin @ W_pred
__device__ float  g_bfused;
__device__ int    g_is64;

__global__ void prep_kernel(const float* __restrict__ W1, const float* __restrict__ as1,
                            const float* __restrict__ ad1,
                            const float* __restrict__ W2, const float* __restrict__ as2,
                            const float* __restrict__ ad2,
                            const float* __restrict__ Wlin, const float* __restrict__ blin,
                            const float* __restrict__ Wpred, const float* __restrict__ bpred,
                            const int* __restrict__ edges)
{
    int tid = blockIdx.x * blockDim.x + threadIdx.x;
    int nt  = gridDim.x * blockDim.x;

    for (int i = tid; i < 32 * 256; i += nt) {
        int ks = i >> 8, c = i & 255;
        g_Wi1[i] = make_float4(W1[(4*ks+0)*NO + c], W1[(4*ks+1)*NO + c],
                               W1[(4*ks+2)*NO + c], W1[(4*ks+3)*NO + c]);
    }
    for (int i = tid; i < 16 * 256; i += nt) {
        int ks = i >> 8, c = i & 255;
        g_Wi2[i] = make_float4(W2[(4*ks+0)*NO + c], W2[(4*ks+1)*NO + c],
                               W2[(4*ks+2)*NO + c], W2[(4*ks+3)*NO + c]);
    }
    for (int i = tid; i < 8 * 128; i += nt) {
        int j = i >> 7, k = i & 127;
        int hh = j & 3;
        const float* av = (j < 4) ? as1 : ad1;
        float s = 0.f;
        for (int c = 0; c < NC; c++)
            s = fmaf(W1[k*NO + hh*NC + c], av[hh*NC + c], s);
        g_waSD1[i] = s;
    }
    for (int i = tid; i < 8 * 64; i += nt) {
        int j = i >> 6, k = i & 63;
        int hh = j & 3;
        const float* av = (j < 4) ? as2 : ad2;
        float s = 0.f;
        for (int c = 0; c < NC; c++)
            s = fmaf(W2[k*NO + hh*NC + c], av[hh*NC + c], s);
        g_waSD2[i] = s;
    }
    for (int i = tid; i < NN * NC; i += nt) {
        float s = 0.f;
        #pragma unroll
        for (int j = 0; j < NC/2; j++) s = fmaf(Wlin[i*(NC/2) + j], Wpred[j], s);
        g_wfused[i] = s;
    }
    if (tid == 0) {
        float s = bpred[0];
        #pragma unroll
        for (int j = 0; j < NC/2; j++) s = fmaf(blin[j], Wpred[j], s);
        g_bfused = s;
        int any = 0;
        #pragma unroll
        for (int k = 1; k < 256; k += 2) any |= edges[k];
        g_is64 = (any == 0) ? 1 : 0;
    }
}

// One GAT layer. xs holds the input [NN,K]; on exit xs[0..NN*NC) holds the
// head-mean (+bias, +optional relu) output.
template<int K, bool RELU>
__device__ __forceinline__ void gat_layer(
    const float4* __restrict__ Wi, const float* __restrict__ waSDt,
    const float* __restrict__ bias,
    float* xs, float* hs, float* os, float* exs, float* Msh,
    float* alj, float* den,
    const int* srcS, const int* dstS, const int* off,
    int NE, int t, int h)
{
    // zero dense attention matrix (written by owner threads later)
    for (int i = t; i < NH*NN*NN; i += 256) Msh[i] = 0.f;

    // ---- GEMM: hs[n][t] = sum_k xs[n][k] * W[k][t] ----
    float acc[NN];
    #pragma unroll
    for (int n = 0; n < NN; n++) acc[n] = 0.f;

    const float4* x4 = (const float4*)xs;
    #pragma unroll 2
    for (int ks = 0; ks < K/4; ks++) {
        float4 w = Wi[ks*NO + t];
        #pragma unroll
        for (int n = 0; n < NN; n++) {
            float4 xv = x4[n*(K/4) + ks];
            float a = acc[n];
            a = fmaf(xv.x, w.x, a);
            a = fmaf(xv.y, w.y, a);
            a = fmaf(xv.z, w.z, a);
            a = fmaf(xv.w, w.w, a);
            acc[n] = a;
        }
    }
    #pragma unroll
    for (int n = 0; n < NN; n++) hs[n*NO + t] = acc[n];

    // ---- attention logits via folded weights: alj[n][j] = x[n,:] . waSDt[j,:] ----
    if (t < NN * 8) {
        int n = t >> 3, j = t & 7;
        const float4* wa = (const float4*)(waSDt + j*K);
        float sx = 0.f, sy = 0.f, sz = 0.f, sw = 0.f;
        #pragma unroll 4
        for (int q = 0; q < K/4; q++) {
            float4 xv = x4[n*(K/4) + q];
            float4 wv = wa[q];
            sx = fmaf(xv.x, wv.x, sx);
            sy = fmaf(xv.y, wv.y, sy);
            sz = fmaf(xv.z, wv.z, sz);
            sw = fmaf(xv.w, wv.w, sw);
        }
        alj[n*8 + j] = (sx + sy) + (sz + sw);
    }
    __syncthreads();

    // ---- per-edge exp(leaky_relu(score)) ----
    for (int i = t; i < NE*NH; i += 256) {
        int e = i >> 2, hh = i & 3;
        float v = alj[srcS[e]*8 + hh] + alj[dstS[e]*8 + 4 + hh];
        v = (v > 0.f) ? v : NEG * v;
        exs[i] = __expf(v);
    }
    __syncthreads();

    // ---- build dense M[h][d][s] + denominator (owner threads, no atomics) ----
    if (t < NN*NH) {
        int d = t >> 2, hh = t & 3;
        float* Mrow = Msh + (hh*NN + d)*NN;
        float dn = 0.f;
        int e1 = off[d+1];
        for (int e = off[d]; e < e1; e++) {
            float ex = exs[e*4 + hh];
            Mrow[srcS[e]] += ex;
            dn += ex;
        }
        den[t] = dn;  // den[d*4+hh]
    }
    __syncthreads();

    // ---- aggregation: os[n][t] = (M[h][n][:] . hs[:,t]) / den[n][h] ----
    float agg[NN];
    #pragma unroll
    for (int n = 0; n < NN; n++) agg[n] = 0.f;
    const float* Mh = Msh + h*NN*NN;
    #pragma unroll
    for (int s = 0; s < NN; s++) {
        float hv = hs[s*NO + t];
        #pragma unroll
        for (int n = 0; n < NN; n++)
            agg[n] = fmaf(Mh[n*NN + s], hv, agg[n]);
    }
    #pragma unroll
    for (int n = 0; n < NN; n++)
        os[n*NO + t] = __fdividef(agg[n], den[n*4 + h]);
    __syncthreads();

    // ---- head mean + bias (+relu) -> xs[0 .. NN*NC) ----
    for (int i = t; i < NN*NC; i += 256) {
        int n = i >> 6, c = i & 63;
        float v = 0.25f * (os[n*NO + c] + os[n*NO + c + 64]
                         + os[n*NO + c + 128] + os[n*NO + c + 192]) + bias[c];
        if (RELU) v = fmaxf(v, 0.f);
        xs[i] = v;
    }
    __syncthreads();
}

__global__ __launch_bounds__(256, 4)
void gat_kernel(const float* __restrict__ feature, const int* __restrict__ eraw,
                const float* __restrict__ b1, const float* __restrict__ b2,
                float* __restrict__ out, int E)
{
    __shared__ __align__(16) float xs[NN*FIN];
    __shared__ float hs[NN*NO];
    __shared__ float os[NN*NO];
    __shared__ float Msh[NH*NN*NN];
    __shared__ float exs[MAXE*NH];
    __shared__ float alj[NN*8];
    __shared__ float den[NN*NH];
    __shared__ int   srcS[MAXE], dstS[MAXE];
    __shared__ int   cnt[NN], off[NN+1];
    __shared__ float red[8];

    const int b = blockIdx.x, t = threadIdx.x;
    const int lane = t & 31, warp = t >> 5, h = t >> 6;
    const int NE = E + NN;
    const int is64 = g_is64;

    if (t < NN) cnt[t] = 0;

    // load features [NN, FIN] (vectorized)
    const float4* xg = (const float4*)(feature + (size_t)b * NN * FIN);
    for (int i = t; i < NN*FIN/4; i += 256) ((float4*)xs)[i] = xg[i];
    __syncthreads();

    // ---- counting sort of edges (incl. self-loops) by dst ----
    for (int e = t; e < NE; e += 256) {
        int d;
        if (e < E) {
            size_t base = ((size_t)b * E + e) * 2;
            d = is64 ? (int)((const long long*)eraw)[base + 1] : eraw[base + 1];
        } else d = e - E;
        atomicAdd(&cnt[d], 1);
    }
    __syncthreads();
    if (t == 0) {
        int s = 0;
        #pragma unroll
        for (int i = 0; i < NN; i++) { off[i] = s; s += cnt[i]; cnt[i] = off[i]; }
        off[NN] = s;
    }
    __syncthreads();
    for (int e = t; e < NE; e += 256) {
        int s, d;
        if (e < E) {
            size_t base = ((size_t)b * E + e) * 2;
            if (is64) { const long long* p = (const long long*)eraw;
                        s = (int)p[base]; d = (int)p[base + 1]; }
            else      { s = eraw[base];   d = eraw[base + 1]; }
        } else { s = d = e - E; }
        int pos = atomicAdd(&cnt[d], 1);
        srcS[pos] = s; dstS[pos] = d;
    }
    __syncthreads();

    gat_layer<FIN, true >(g_Wi1, g_waSD1, b1, xs, hs, os, exs, Msh, alj, den,
                          srcS, dstS, off, NE, t, h);
    gat_layer<NC,  false>(g_Wi2, g_waSD2, b2, xs, hs, os, exs, Msh, alj, den,
                          srcS, dstS, off, NE, t, h);

    // ---- fused head: sigmoid(flat . w_fused + b_fused) ----
    float p = 0.f;
    for (int i = t; i < NN*NC; i += 256) p = fmaf(xs[i], g_wfused[i], p);
    #pragma unroll
    for (int o = 16; o; o >>= 1) p += __shfl_xor_sync(0xffffffffu, p, o);
    if (lane == 0) red[warp] = p;
    __syncthreads();
    if (t == 0) {
        float s = g_bfused;
        #pragma unroll
        for (int w = 0; w < 8; w++) s += red[w];
        out[b] = 1.f / (1.f + __expf(-s));
    }
}

extern "C" void kernel_launch(void* const* d_in, const int* in_sizes, int n_in,
                              void* d_out, int out_size)
{
    const float* feature = (const float*)d_in[0];
    const int*   edges   = (const int*)  d_in[1];
    const float* W1   = (const float*)d_in[2];
    const float* as1  = (const float*)d_in[3];
    const float* ad1  = (const float*)d_in[4];
    const float* b1   = (const float*)d_in[5];
    const float* W2   = (const float*)d_in[6];
    const float* as2  = (const float*)d_in[7];
    const float* ad2  = (const float*)d_in[8];
    const float* b2   = (const float*)d_in[9];
    const float* Wlin = (const float*)d_in[10];
    const float* blin = (const float*)d_in[11];
    const float* Wpred= (const float*)d_in[12];
    const float* bpred= (const float*)d_in[13];

    int B = in_sizes[0] / (NN * FIN);       // 16384
    int E = in_sizes[1] / (2 * B);          // 182

    prep_kernel<<<48, 256>>>(W1, as1, ad1, W2, as2, ad2,
                             Wlin, blin, Wpred, bpred, edges);
    gat_kernel<<<B, 256>>>(feature, edges, b1, b2, (float*)d_out, E);
}

// round 3
// speedup vs baseline: 1.7094x; 1.3688x over previous
#include <cuda_runtime.h>

#define NN 14      // nodes per graph
#define NH 4       // heads
#define NC 64      // per-head channels
#define NO 256     // NH*NC
#define FIN 128
#define NEG 0.2f
#define NT 128     // threads per block (each owns columns t and t+128)
#define MAXE 224   // >= E + NN = 196

typedef unsigned long long ull;

__device__ __forceinline__ ull pk2(float x, float y) {
    ull r; asm("mov.b64 %0, {%1, %2};" : "=l"(r) : "f"(x), "f"(y)); return r;
}
__device__ __forceinline__ ull fma2(ull a, ull b, ull c) {
    ull d; asm("fma.rn.f32x2 %0, %1, %2, %3;" : "=l"(d) : "l"(a), "l"(b), "l"(c)); return d;
}

// ---- precomputed weights (filled by prep_kernel) ----
// Wp[kp][t] = (W[2kp][t], W[2kp][t+128], W[2kp+1][t], W[2kp+1][t+128])
__device__ float4 g_Wp1[64 * 128];
__device__ float4 g_Wp2[32 * 128];
__device__ float  g_waSD1[8 * 128];   // j=0..3: W1[:,h]@a_src1[h]; j=4..7: a_dst1
__device__ float  g_waSD2[8 * 64];
__device__ float  g_wfused[NN * NC];  // W_lin @ W_pred
__device__ float  g_bfused;
__device__ int    g_is64;

__global__ void prep_kernel(const float* __restrict__ W1, const float* __restrict__ as1,
                            const float* __restrict__ ad1,
                            const float* __restrict__ W2, const float* __restrict__ as2,
                            const float* __restrict__ ad2,
                            const float* __restrict__ Wlin, const float* __restrict__ blin,
                            const float* __restrict__ Wpred, const float* __restrict__ bpred,
                            const int* __restrict__ edges)
{
    int tid = blockIdx.x * blockDim.x + threadIdx.x;
    int nt  = gridDim.x * blockDim.x;

    for (int i = tid; i < 64 * 128; i += nt) {
        int kp = i >> 7, t = i & 127;
        g_Wp1[i] = make_float4(W1[(2*kp)*NO + t],     W1[(2*kp)*NO + t + 128],
                               W1[(2*kp+1)*NO + t],   W1[(2*kp+1)*NO + t + 128]);
    }
    for (int i = tid; i < 32 * 128; i += nt) {
        int kp = i >> 7, t = i & 127;
        g_Wp2[i] = make_float4(W2[(2*kp)*NO + t],     W2[(2*kp)*NO + t + 128],
                               W2[(2*kp+1)*NO + t],   W2[(2*kp+1)*NO + t + 128]);
    }
    for (int i = tid; i < 8 * 128; i += nt) {
        int j = i >> 7, k = i & 127;
        int hh = j & 3;
        const float* av = (j < 4) ? as1 : ad1;
        float s = 0.f;
        for (int c = 0; c < NC; c++)
            s = fmaf(W1[k*NO + hh*NC + c], av[hh*NC + c], s);
        g_waSD1[i] = s;
    }
    for (int i = tid; i < 8 * 64; i += nt) {
        int j = i >> 6, k = i & 63;
        int hh = j & 3;
        const float* av = (j < 4) ? as2 : ad2;
        float s = 0.f;
        for (int c = 0; c < NC; c++)
            s = fmaf(W2[k*NO + hh*NC + c], av[hh*NC + c], s);
        g_waSD2[i] = s;
    }
    for (int i = tid; i < NN * NC; i += nt) {
        float s = 0.f;
        #pragma unroll
        for (int j = 0; j < NC/2; j++) s = fmaf(Wlin[i*(NC/2) + j], Wpred[j], s);
        g_wfused[i] = s;
    }
    if (tid == 0) {
        float s = bpred[0];
        #pragma unroll
        for (int j = 0; j < NC/2; j++) s = fmaf(blin[j], Wpred[j], s);
        g_bfused = s;
        int any = 0;
        #pragma unroll
        for (int k = 1; k < 256; k += 2) any |= edges[k];
        g_is64 = (any == 0) ? 1 : 0;
    }
}

// One GAT layer. xs input [NN rows, stride 4*XS4 floats]; output (head-mean +
// bias (+relu)) written to xs at stride 68 floats.
template<int K, int XS4, bool RELU>
__device__ __forceinline__ void gat_layer(
    const ulonglong2* __restrict__ Wp, const float4* __restrict__ waSD,
    const float* __restrict__ bias,
    float* xs, ull* hs2, float* M2, float* exs, float* alj,
    const int* srcS, const int* dstS, const int* off,
    int NE, int t)
{
    // zero paired attention matrix (written by owner threads after next sync)
    for (int i = t; i < 2*NN*NN*2; i += NT) M2[i] = 0.f;

    const float4* x4 = (const float4*)xs;

    // ---- GEMM: column-pair (t, t+128) per thread, packed f32x2 ----
    ull acc[NN];
    #pragma unroll
    for (int n = 0; n < NN; n++) acc[n] = 0ull;

    #pragma unroll 2
    for (int ks = 0; ks < K/4; ks++) {
        ulonglong2 wA = Wp[ks*256 + t];
        ulonglong2 wB = Wp[ks*256 + 128 + t];
        #pragma unroll
        for (int n = 0; n < NN; n++) {
            float4 xv = x4[n*XS4 + ks];
            ull a = acc[n];
            a = fma2(wA.x, pk2(xv.x, xv.x), a);
            a = fma2(wA.y, pk2(xv.y, xv.y), a);
            a = fma2(wB.x, pk2(xv.z, xv.z), a);
            a = fma2(wB.y, pk2(xv.w, xv.w), a);
            acc[n] = a;
        }
    }
    #pragma unroll
    for (int n = 0; n < NN; n++) hs2[n*NT + t] = acc[n];

    // ---- attention logits via folded weights: alj[n][j] = x[n,:].waSD[j,:] ----
    if (t < NN * 8) {
        int n = t >> 3, j = t & 7;
        const float4* wa = waSD + j*(K/4);
        float sx = 0.f, sy = 0.f, sz = 0.f, sw = 0.f;
        #pragma unroll 4
        for (int q = 0; q < K/4; q++) {
            float4 xv = x4[n*XS4 + q];
            float4 wv = wa[q];
            sx = fmaf(xv.x, wv.x, sx);
            sy = fmaf(xv.y, wv.y, sy);
            sz = fmaf(xv.z, wv.z, sz);
            sw = fmaf(xv.w, wv.w, sw);
        }
        alj[n*8 + j] = (sx + sy) + (sz + sw);
    }
    __syncthreads();

    // ---- per-edge exp(leaky_relu(score)) ----
    for (int i = t; i < NE*NH; i += NT) {
        int e = i >> 2, hh = i & 3;
        float v = alj[srcS[e]*8 + hh] + alj[dstS[e]*8 + 4 + hh];
        v = (v > 0.f) ? v : NEG * v;
        exs[i] = __expf(v);
    }
    __syncthreads();

    // ---- build normalized dense attention, packed as head-pairs:
    //      M2 float2 at ull-index (p*NN+d)*NN+s holds (alpha[h=p], alpha[h=p+2])
    if (t < NN*NH) {
        int d = t >> 2, hh = t & 3;
        float* Mrow = M2 + ((hh & 1)*NN + d)*(NN*2) + (hh >> 1);
        float dn = 0.f;
        int e1 = off[d+1];
        for (int e = off[d]; e < e1; e++) {
            float ex = exs[e*4 + hh];
            Mrow[srcS[e]*2] += ex;
            dn += ex;
        }
        float inv = __fdividef(1.f, dn);
        #pragma unroll
        for (int s = 0; s < NN; s++) Mrow[s*2] *= inv;
    }
    __syncthreads();

    // ---- aggregation: column-private, result overwrites hs2 ----
    {
        const ull* Mp = (const ull*)M2 + (t >> 6) * (NN*NN);
        ull agg[NN];
        #pragma unroll
        for (int n = 0; n < NN; n++) agg[n] = 0ull;
        #pragma unroll
        for (int s = 0; s < NN; s++) {
            ull hv = hs2[s*NT + t];
            #pragma unroll
            for (int n = 0; n < NN; n++)
                agg[n] = fma2(Mp[n*NN + s], hv, agg[n]);
        }
        #pragma unroll
        for (int n = 0; n < NN; n++) hs2[n*NT + t] = agg[n];
    }
    __syncthreads();

    // ---- head mean + bias (+relu) -> xs (stride 68 floats) ----
    const float2* h2f = (const float2*)hs2;
    for (int i = t; i < NN*NC; i += NT) {
        int n = i >> 6, c = i & 63;
        float2 A  = h2f[n*NT + c];
        float2 Bv = h2f[n*NT + c + 64];
        float v = 0.25f * ((A.x + A.y) + (Bv.x + Bv.y)) + bias[c];
        if (RELU) v = fmaxf(v, 0.f);
        xs[n*68 + c] = v;
    }
    __syncthreads();
}

__global__ void __launch_bounds__(NT, 6)
gat_kernel(const float* __restrict__ feature, const int* __restrict__ eraw,
           const float* __restrict__ b1, const float* __restrict__ b2,
           float* __restrict__ out, int E)
{
    __shared__ __align__(16) float xs[NN*132];      // padded input rows
    __shared__ __align__(16) ull   hs2[NN*NT];      // per-node column pairs
    __shared__ __align__(16) float M2[2*NN*NN*2];   // head-paired attention
    __shared__ float exs[MAXE*NH];
    __shared__ float alj[NN*8];
    __shared__ int   srcS[MAXE], dstS[MAXE];
    __shared__ int   cnt[NN], off[NN+1];
    __shared__ float red[4];

    const int b = blockIdx.x, t = threadIdx.x;
    const int lane = t & 31, warp = t >> 5;
    const int NE = E + NN;
    const int is64 = g_is64;

    if (t < NN) cnt[t] = 0;

    // load features into padded xs (stride 33 float4 per row)
    const float4* xg = (const float4*)(feature + (size_t)b * NN * FIN);
    for (int i = t; i < NN*FIN/4; i += NT) {
        int n = i >> 5, k4 = i & 31;
        ((float4*)xs)[n*33 + k4] = xg[i];
    }
    __syncthreads();

    // ---- counting sort of edges (incl. self-loops) by dst ----
    for (int e = t; e < NE; e += NT) {
        int d;
        if (e < E) {
            size_t base = ((size_t)b * E + e) * 2;
            d = is64 ? (int)((const long long*)eraw)[base + 1] : eraw[base + 1];
        } else d = e - E;
        atomicAdd(&cnt[d], 1);
    }
    __syncthreads();
    if (t == 0) {
        int s = 0;
        #pragma unroll
        for (int i = 0; i < NN; i++) { off[i] = s; s += cnt[i]; cnt[i] = off[i]; }
        off[NN] = s;
    }
    __syncthreads();
    for (int e = t; e < NE; e += NT) {
        int s, d;
        if (e < E) {
            size_t base = ((size_t)b * E + e) * 2;
            if (is64) { const long long* p = (const long long*)eraw;
                        s = (int)p[base]; d = (int)p[base + 1]; }
            else      { s = eraw[base];   d = eraw[base + 1]; }
        } else { s = d = e - E; }
        int pos = atomicAdd(&cnt[d], 1);
        srcS[pos] = s; dstS[pos] = d;
    }
    __syncthreads();

    gat_layer<FIN, 33, true >((const ulonglong2*)g_Wp1, (const float4*)g_waSD1, b1,
                              xs, hs2, M2, exs, alj, srcS, dstS, off, NE, t);
    gat_layer<NC,  17, false>((const ulonglong2*)g_Wp2, (const float4*)g_waSD2, b2,
                              xs, hs2, M2, exs, alj, srcS, dstS, off, NE, t);

    // ---- fused head: sigmoid(flat . w_fused + b_fused) ----
    float p = 0.f;
    for (int i = t; i < NN*NC; i += NT) {
        int n = i >> 6, c = i & 63;
        p = fmaf(xs[n*68 + c], g_wfused[i], p);
    }
    #pragma unroll
    for (int o = 16; o; o >>= 1) p += __shfl_xor_sync(0xffffffffu, p, o);
    if (lane == 0) red[warp] = p;
    __syncthreads();
    if (t == 0) {
        float s = g_bfused + ((red[0] + red[1]) + (red[2] + red[3]));
        out[b] = 1.f / (1.f + __expf(-s));
    }
}

extern "C" void kernel_launch(void* const* d_in, const int* in_sizes, int n_in,
                              void* d_out, int out_size)
{
    const float* feature = (const float*)d_in[0];
    const int*   edges   = (const int*)  d_in[1];
    const float* W1   = (const float*)d_in[2];
    const float* as1  = (const float*)d_in[3];
    const float* ad1  = (const float*)d_in[4];
    const float* b1   = (const float*)d_in[5];
    const float* W2   = (const float*)d_in[6];
    const float* as2  = (const float*)d_in[7];
    const float* ad2  = (const float*)d_in[8];
    const float* b2   = (const float*)d_in[9];
    const float* Wlin = (const float*)d_in[10];
    const float* blin = (const float*)d_in[11];
    const float* Wpred= (const float*)d_in[12];
    const float* bpred= (const float*)d_in[13];

    int B = in_sizes[0] / (NN * FIN);       // 16384
    int E = in_sizes[1] / (2 * B);          // 182

    prep_kernel<<<48, 256>>>(W1, as1, ad1, W2, as2, ad2,
                             Wlin, blin, Wpred, bpred, edges);
    gat_kernel<<<B, NT>>>(feature, edges, b1, b2, (float*)d_out, E);
}

// round 5
// speedup vs baseline: 1.9727x; 1.1540x over previous
#include <cuda_runtime.h>

#define NN 14      // nodes per graph
#define NH 4       // heads
#define NC 64      // per-head channels
#define NO 256     // NH*NC
#define FIN 128
#define NEG 0.2f
#define NT 128     // threads per block
#define MAXE 224   // >= E + NN = 196

typedef unsigned long long ull;

__device__ __forceinline__ ull pk2(float x, float y) {
    ull r; asm("mov.b64 %0, {%1, %2};" : "=l"(r) : "f"(x), "f"(y)); return r;
}
__device__ __forceinline__ void upk2(ull v, float& x, float& y) {
    asm("mov.b64 {%0, %1}, %2;" : "=f"(x), "=f"(y) : "l"(v));
}
__device__ __forceinline__ ull fma2(ull a, ull b, ull c) {
    ull d; asm("fma.rn.f32x2 %0, %1, %2, %3;" : "=l"(d) : "l"(a), "l"(b), "l"(c)); return d;
}
__device__ __forceinline__ ull add2(ull a, ull b) {
    ull d; asm("add.rn.f32x2 %0, %1, %2;" : "=l"(d) : "l"(a), "l"(b)); return d;
}

// ---- precomputed weights (filled by prep_kernel) ----
// Wp[kp*128+t] = (W[2kp][t], W[2kp][t+128], W[2kp+1][t], W[2kp+1][t+128])
__device__ float4 g_Wp1[64 * 128];
__device__ float4 g_Wp2[32 * 128];
__device__ float  g_waSD1[8 * 128];   // j=0..3: W1[:,h]@a_src1[h]; j=4..7: a_dst1
__device__ float  g_waSD2[8 * 64];
__device__ float  g_wfused[NN * NC];  // W_lin @ W_pred
__device__ float  g_bfused;
__device__ int    g_is64;

__global__ void prep_kernel(const float* __restrict__ W1, const float* __restrict__ as1,
                            const float* __restrict__ ad1,
                            const float* __restrict__ W2, const float* __restrict__ as2,
                            const float* __restrict__ ad2,
                            const float* __restrict__ Wlin, const float* __restrict__ blin,
                            const float* __restrict__ Wpred, const float* __restrict__ bpred,
                            const int* __restrict__ edges)
{
    int tid = blockIdx.x * blockDim.x + threadIdx.x;
    int nt  = gridDim.x * blockDim.x;

    for (int i = tid; i < 64 * 128; i += nt) {
        int kp = i >> 7, t = i & 127;
        g_Wp1[i] = make_float4(W1[(2*kp)*NO + t],   W1[(2*kp)*NO + t + 128],
                               W1[(2*kp+1)*NO + t], W1[(2*kp+1)*NO + t + 128]);
    }
    for (int i = tid; i < 32 * 128; i += nt) {
        int kp = i >> 7, t = i & 127;
        g_Wp2[i] = make_float4(W2[(2*kp)*NO + t],   W2[(2*kp)*NO + t + 128],
                               W2[(2*kp+1)*NO + t], W2[(2*kp+1)*NO + t + 128]);
    }
    for (int i = tid; i < 8 * 128; i += nt) {
        int j = i >> 7, k = i & 127;
        int hh = j & 3;
        const float* av = (j < 4) ? as1 : ad1;
        float s = 0.f;
        for (int c = 0; c < NC; c++)
            s = fmaf(W1[k*NO + hh*NC + c], av[hh*NC + c], s);
        g_waSD1[i] = s;
    }
    for (int i = tid; i < 8 * 64; i += nt) {
        int j = i >> 6, k = i & 63;
        int hh = j & 3;
        const float* av = (j < 4) ? as2 : ad2;
        float s = 0.f;
        for (int c = 0; c < NC; c++)
            s = fmaf(W2[k*NO + hh*NC + c], av[hh*NC + c], s);
        g_waSD2[i] = s;
    }
    for (int i = tid; i < NN * NC; i += nt) {
        float s = 0.f;
        #pragma unroll
        for (int j = 0; j < NC/2; j++) s = fmaf(Wlin[i*(NC/2) + j], Wpred[j], s);
        g_wfused[i] = s;
    }
    if (tid == 0) {
        float s = bpred[0];
        #pragma unroll
        for (int j = 0; j < NC/2; j++) s = fmaf(blin[j], Wpred[j], s);
        g_bfused = s;
        int any = 0;
        #pragma unroll
        for (int k = 1; k < 256; k += 2) any |= edges[k];
        g_is64 = (any == 0) ? 1 : 0;
    }
}

// One GAT layer for a GRAPH PAIR. xs2: interleaved (g0,g1) pairs per k,
// ulonglong2 row stride S2. Output written back to xs2 at ull stride 66.
template<int K, int S2, bool RELU>
__device__ __forceinline__ void gat_layer(
    const float4* __restrict__ Wp, const float* __restrict__ waSD,
    const float* __restrict__ bias,
    ull* xs2, ull* hs2, ull* Mpk, float* exsf, ull* aljp,
    const int (*srcS)[MAXE], const int (*dstS)[MAXE], const int (*off)[NN+1],
    int NE, int t)
{
    // zero paired attention matrix
    for (int i = t; i < NH*NN*NN; i += NT) Mpk[i] = 0ull;

    const ulonglong2* xu2 = (const ulonglong2*)xs2;

    // ---- GEMM: cols (t, t+128), graphs packed in f32x2 lanes ----
    ull aA[NN], aB[NN];
    #pragma unroll
    for (int n = 0; n < NN; n++) { aA[n] = 0ull; aB[n] = 0ull; }

    #pragma unroll 2
    for (int ks = 0; ks < K/4; ks++) {
        float4 f1 = Wp[ks*256 + t];
        float4 f2 = Wp[ks*256 + 128 + t];
        ull w0A = pk2(f1.x, f1.x), w0B = pk2(f1.y, f1.y);
        ull w1A = pk2(f1.z, f1.z), w1B = pk2(f1.w, f1.w);
        ull w2A = pk2(f2.x, f2.x), w2B = pk2(f2.y, f2.y);
        ull w3A = pk2(f2.z, f2.z), w3B = pk2(f2.w, f2.w);
        #pragma unroll
        for (int n = 0; n < NN; n++) {
            ulonglong2 x01 = xu2[n*S2 + 2*ks];
            ulonglong2 x23 = xu2[n*S2 + 2*ks + 1];
            ull a = aA[n];
            a = fma2(w0A, x01.x, a);
            a = fma2(w1A, x01.y, a);
            a = fma2(w2A, x23.x, a);
            a = fma2(w3A, x23.y, a);
            aA[n] = a;
            ull b = aB[n];
            b = fma2(w0B, x01.x, b);
            b = fma2(w1B, x01.y, b);
            b = fma2(w2B, x23.x, b);
            b = fma2(w3B, x23.y, b);
            aB[n] = b;
        }
    }
    #pragma unroll
    for (int n = 0; n < NN; n++) {
        hs2[n*NO + t]       = aA[n];
        hs2[n*NO + 128 + t] = aB[n];
    }

    // ---- attention logits (both graphs packed): aljp[n*8+j] ----
    if (t < NN * 8) {
        int n = t >> 3, j = t & 7;
        const float4* wa = (const float4*)(waSD + j*K);
        ull s0 = 0ull, s1 = 0ull, s2 = 0ull, s3 = 0ull;
        #pragma unroll 4
        for (int q = 0; q < K/4; q++) {
            float4 w = wa[q];
            ulonglong2 xa = xu2[n*S2 + 2*q];
            ulonglong2 xb = xu2[n*S2 + 2*q + 1];
            s0 = fma2(xa.x, pk2(w.x, w.x), s0);
            s1 = fma2(xa.y, pk2(w.y, w.y), s1);
            s2 = fma2(xb.x, pk2(w.z, w.z), s2);
            s3 = fma2(xb.y, pk2(w.w, w.w), s3);
        }
        aljp[n*8 + j] = add2(add2(s0, s1), add2(s2, s3));
    }
    __syncthreads();

    // ---- per-edge exp(leaky_relu(score)), both graphs ----
    const float* aljf = (const float*)aljp;
    for (int i = t; i < 2*NE*NH; i += NT) {
        int g  = (i < NE*NH) ? 0 : 1;
        int ii = i - g*NE*NH;
        int e = ii >> 2, hh = ii & 3;
        float v = aljf[(srcS[g][e]*8 + hh)*2 + g]
                + aljf[(dstS[g][e]*8 + 4 + hh)*2 + g];
        v = (v > 0.f) ? v : NEG * v;
        exsf[g*MAXE*NH + ii] = __expf(v);
    }
    __syncthreads();

    // ---- build normalized attention, packed (g0,g1): Mpk[h][d][s] ----
    if (t < 2*NN*NH) {
        int g = t / (NN*NH), r = t - g*(NN*NH);
        int d = r >> 2, hh = r & 3;
        float* Mrow = (float*)Mpk + ((hh*NN + d)*NN)*2 + g;
        const float* ex = exsf + g*MAXE*NH;
        float dn = 0.f;
        int e1 = off[g][d+1];
        for (int e = off[g][d]; e < e1; e++) {
            float v = ex[e*4 + hh];
            Mrow[srcS[g][e]*2] += v;
            dn += v;
        }
        float inv = __fdividef(1.f, dn);
        #pragma unroll
        for (int s = 0; s < NN; s++) Mrow[s*2] *= inv;
    }
    __syncthreads();

    // ---- aggregation (column-private, packed graphs) ----
    {
        int p = t >> 6;                       // head of col t; col t+128 -> p+2
        const ull* M0 = Mpk + p*NN*NN;
        const ull* M2 = Mpk + (p+2)*NN*NN;
        #pragma unroll
        for (int n = 0; n < NN; n++) { aA[n] = 0ull; aB[n] = 0ull; }
        #pragma unroll
        for (int s = 0; s < NN; s++) {
            ull hvA = hs2[s*NO + t];
            ull hvB = hs2[s*NO + 128 + t];
            #pragma unroll
            for (int n = 0; n < NN; n++) {
                aA[n] = fma2(M0[n*NN + s], hvA, aA[n]);
                aB[n] = fma2(M2[n*NN + s], hvB, aB[n]);
            }
        }
        #pragma unroll
        for (int n = 0; n < NN; n++) {
            hs2[n*NO + t]       = aA[n];
            hs2[n*NO + 128 + t] = aB[n];
        }
    }
    __syncthreads();

    // ---- head mean + bias (+relu) -> xs2 (ull stride 66) ----
    const ull quart = pk2(0.25f, 0.25f);
    for (int i = t; i < NN*NC; i += NT) {
        int n = i >> 6, c = i & 63;
        ull v = add2(add2(hs2[n*NO + c],       hs2[n*NO + 64 + c]),
                     add2(hs2[n*NO + 128 + c], hs2[n*NO + 192 + c]));
        float bb = bias[c];
        v = fma2(v, quart, pk2(bb, bb));
        if (RELU) {
            float x, y; upk2(v, x, y);
            v = pk2(fmaxf(x, 0.f), fmaxf(y, 0.f));
        }
        xs2[n*66 + c] = v;
    }
    __syncthreads();
}

__global__ void __launch_bounds__(NT, 3)
gat_kernel(const float* __restrict__ feature, const int* __restrict__ eraw,
           const float* __restrict__ b1v, const float* __restrict__ b2v,
           float* __restrict__ out, int B, int E)
{
    __shared__ __align__(16) ull xs2[NN*130];    // paired features / layer IO
    __shared__ __align__(16) ull hs2[NN*NO];     // paired per-node columns
    __shared__ __align__(16) ull Mpk[NH*NN*NN];  // paired attention matrix
    __shared__ float exsf[2*MAXE*NH];
    __shared__ ull   aljp[NN*8];
    __shared__ int   srcS[2][MAXE], dstS[2][MAXE];
    __shared__ int   cnt[2][NN], off[2][NN+1];
    __shared__ float2 red[4];

    const int t = threadIdx.x;
    const int lane = t & 31, warp = t >> 5;
    const int g0 = 2*blockIdx.x;
    const int g1 = (g0 + 1 < B) ? g0 + 1 : g0;
    const int NE = E + NN;
    const int is64 = g_is64;

    if (t < NN) { cnt[0][t] = 0; cnt[1][t] = 0; }

    // load + interleave features of both graphs
    {
        const float4* xg0 = (const float4*)(feature + (size_t)g0 * NN * FIN);
        const float4* xg1 = (const float4*)(feature + (size_t)g1 * NN * FIN);
        ulonglong2* xo = (ulonglong2*)xs2;
        for (int i = t; i < NN*FIN/4; i += NT) {
            int n = i >> 5, k4 = i & 31;
            float4 a0 = xg0[n*32 + k4];
            float4 a1 = xg1[n*32 + k4];
            ulonglong2 v0, v1;
            v0.x = pk2(a0.x, a1.x); v0.y = pk2(a0.y, a1.y);
            v1.x = pk2(a0.z, a1.z); v1.y = pk2(a0.w, a1.w);
            xo[n*65 + 2*k4]     = v0;
            xo[n*65 + 2*k4 + 1] = v1;
        }
    }
    __syncthreads();

    // ---- counting sort of both graphs' edges by dst ----
    #pragma unroll
    for (int g = 0; g < 2; g++) {
        int bg = g ? g1 : g0;
        for (int e = t; e < NE; e += NT) {
            int d;
            if (e < E) {
                size_t base = ((size_t)bg * E + e) * 2;
                d = is64 ? (int)((const long long*)eraw)[base + 1] : eraw[base + 1];
            } else d = e - E;
            atomicAdd(&cnt[g][d], 1);
        }
    }
    __syncthreads();
    if (t < 2) {
        int s = 0;
        #pragma unroll
        for (int i = 0; i < NN; i++) { off[t][i] = s; s += cnt[t][i]; cnt[t][i] = off[t][i]; }
        off[t][NN] = s;
    }
    __syncthreads();
    #pragma unroll
    for (int g = 0; g < 2; g++) {
        int bg = g ? g1 : g0;
        for (int e = t; e < NE; e += NT) {
            int s, d;
            if (e < E) {
                size_t base = ((size_t)bg * E + e) * 2;
                if (is64) { const long long* p = (const long long*)eraw;
                            s = (int)p[base]; d = (int)p[base + 1]; }
                else      { s = eraw[base];   d = eraw[base + 1]; }
            } else { s = d = e - E; }
            int pos = atomicAdd(&cnt[g][d], 1);
            srcS[g][pos] = s; dstS[g][pos] = d;
        }
    }
    __syncthreads();

    gat_layer<FIN, 65, true >(g_Wp1, g_waSD1, b1v, xs2, hs2, Mpk, exsf, aljp,
                              srcS, dstS, off, NE, t);
    gat_layer<NC,  33, false>(g_Wp2, g_waSD2, b2v, xs2, hs2, Mpk, exsf, aljp,
                              srcS, dstS, off, NE, t);

    // ---- fused head: both graphs at once ----
    ull pp = 0ull;
    for (int i = t; i < NN*NC; i += NT) {
        int n = i >> 6, c = i & 63;
        float w = g_wfused[i];
        pp = fma2(xs2[n*66 + c], pk2(w, w), pp);
    }
    float px, py; upk2(pp, px, py);
    #pragma unroll
    for (int o = 16; o; o >>= 1) {
        px += __shfl_xor_sync(0xffffffffu, px, o);
        py += __shfl_xor_sync(0xffffffffu, py, o);
    }
    if (lane == 0) red[warp] = make_float2(px, py);
    __syncthreads();
    if (t == 0) {
        float sx = g_bfused, sy = g_bfused;
        #pragma unroll
        for (int w = 0; w < 4; w++) { sx += red[w].x; sy += red[w].y; }
        out[g0] = 1.f / (1.f + __expf(-sx));
        out[g1] = 1.f / (1.f + __expf(-sy));
    }
}

extern "C" void kernel_launch(void* const* d_in, const int* in_sizes, int n_in,
                              void* d_out, int out_size)
{
    const float* feature = (const float*)d_in[0];
    const int*   edges   = (const int*)  d_in[1];
    const float* W1   = (const float*)d_in[2];
    const float* as1  = (const float*)d_in[3];
    const float* ad1  = (const float*)d_in[4];
    const float* b1   = (const float*)d_in[5];
    const float* W2   = (const float*)d_in[6];
    const float* as2  = (const float*)d_in[7];
    const float* ad2  = (const float*)d_in[8];
    const float* b2   = (const float*)d_in[9];
    const float* Wlin = (const float*)d_in[10];
    const float* blin = (const float*)d_in[11];
    const float* Wpred= (const float*)d_in[12];
    const float* bpred= (const float*)d_in[13];

    int B = in_sizes[0] / (NN * FIN);       // 16384
    int E = in_sizes[1] / (2 * B);          // 182

    prep_kernel<<<48, 256>>>(W1, as1, ad1, W2, as2, ad2,
                             Wlin, blin, Wpred, bpred, edges);
    int Bp = (B + 1) / 2;
    gat_kernel<<<Bp, NT>>>(feature, edges, b1, b2, (float*)d_out, B, E);
}

// round 6
// speedup vs baseline: 2.1580x; 1.0939x over previous
#include <cuda_runtime.h>

#define NN 14      // nodes per graph
#define NH 4       // heads
#define NC 64      // per-head channels
#define NO 256     // NH*NC
#define FIN 128
#define NEG 0.2f
#define NT 128     // threads per block
#define MAXE 224   // >= E + NN = 196

typedef unsigned long long ull;

__device__ __forceinline__ ull pk2(float x, float y) {
    ull r; asm("mov.b64 %0, {%1, %2};" : "=l"(r) : "f"(x), "f"(y)); return r;
}
__device__ __forceinline__ void upk2(ull v, float& x, float& y) {
    asm("mov.b64 {%0, %1}, %2;" : "=f"(x), "=f"(y) : "l"(v));
}
__device__ __forceinline__ ull fma2(ull a, ull b, ull c) {
    ull d; asm("fma.rn.f32x2 %0, %1, %2, %3;" : "=l"(d) : "l"(a), "l"(b), "l"(c)); return d;
}
__device__ __forceinline__ ull add2(ull a, ull b) {
    ull d; asm("add.rn.f32x2 %0, %1, %2;" : "=l"(d) : "l"(a), "l"(b)); return d;
}

// ---- precomputed weights (filled by prep_kernel) ----
// Column pairing: thread t owns colA = (t>>5)*64 + (t&31) and colB = colA+32
// (both in head p = t>>5).  Wp[kp*128+t] = (W[2kp][cA], W[2kp][cB],
//                                           W[2kp+1][cA], W[2kp+1][cB])
__device__ float4 g_Wp1[64 * 128];
__device__ float4 g_Wp2[32 * 128];
__device__ float  g_waSD1[8 * 128];   // j=0..3: W1[:,h]@a_src1[h]; j=4..7: a_dst1
__device__ float  g_waSD2[8 * 64];
__device__ float  g_wfused[NN * NC];  // W_lin @ W_pred
__device__ float  g_bfused;
__device__ int    g_is64;

__global__ void prep_kernel(const float* __restrict__ W1, const float* __restrict__ as1,
                            const float* __restrict__ ad1,
                            const float* __restrict__ W2, const float* __restrict__ as2,
                            const float* __restrict__ ad2,
                            const float* __restrict__ Wlin, const float* __restrict__ blin,
                            const float* __restrict__ Wpred, const float* __restrict__ bpred,
                            const int* __restrict__ edges)
{
    int tid = blockIdx.x * blockDim.x + threadIdx.x;
    int nt  = gridDim.x * blockDim.x;

    for (int i = tid; i < 64 * 128; i += nt) {
        int kp = i >> 7, t = i & 127;
        int cA = ((t >> 5) << 6) + (t & 31), cB = cA + 32;
        g_Wp1[i] = make_float4(W1[(2*kp)*NO + cA],   W1[(2*kp)*NO + cB],
                               W1[(2*kp+1)*NO + cA], W1[(2*kp+1)*NO + cB]);
    }
    for (int i = tid; i < 32 * 128; i += nt) {
        int kp = i >> 7, t = i & 127;
        int cA = ((t >> 5) << 6) + (t & 31), cB = cA + 32;
        g_Wp2[i] = make_float4(W2[(2*kp)*NO + cA],   W2[(2*kp)*NO + cB],
                               W2[(2*kp+1)*NO + cA], W2[(2*kp+1)*NO + cB]);
    }
    for (int i = tid; i < 8 * 128; i += nt) {
        int j = i >> 7, k = i & 127;
        int hh = j & 3;
        const float* av = (j < 4) ? as1 : ad1;
        float s = 0.f;
        for (int c = 0; c < NC; c++)
            s = fmaf(W1[k*NO + hh*NC + c], av[hh*NC + c], s);
        g_waSD1[i] = s;
    }
    for (int i = tid; i < 8 * 64; i += nt) {
        int j = i >> 6, k = i & 63;
        int hh = j & 3;
        const float* av = (j < 4) ? as2 : ad2;
        float s = 0.f;
        for (int c = 0; c < NC; c++)
            s = fmaf(W2[k*NO + hh*NC + c], av[hh*NC + c], s);
        g_waSD2[i] = s;
    }
    for (int i = tid; i < NN * NC; i += nt) {
        float s = 0.f;
        #pragma unroll
        for (int j = 0; j < NC/2; j++) s = fmaf(Wlin[i*(NC/2) + j], Wpred[j], s);
        g_wfused[i] = s;
    }
    if (tid == 0) {
        float s = bpred[0];
        #pragma unroll
        for (int j = 0; j < NC/2; j++) s = fmaf(blin[j], Wpred[j], s);
        g_bfused = s;
        int any = 0;
        #pragma unroll
        for (int k = 1; k < 256; k += 2) any |= edges[k];
        g_is64 = (any == 0) ? 1 : 0;
    }
}

// One GAT layer for a GRAPH PAIR, GEMM + aggregation in registers.
// xs2: interleaved (g0,g1) pairs per k, ulonglong2 row stride S2.
// Output (head-mean + bias (+relu)) written back to xs2 at ull stride 66.
template<int K, int S2, bool RELU>
__device__ __forceinline__ void gat_layer(
    const float4* __restrict__ Wp, const float* __restrict__ waSD,
    const float* __restrict__ bias,
    ull* xs2, ull* hs2, ull* Mpk, ull* aljp,
    const int (*srcS)[MAXE], const int (*off)[NN+1],
    int t)
{
    // zero paired attention matrix (visible after the next sync)
    for (int i = t; i < NH*NN*NN; i += NT) Mpk[i] = 0ull;

    const ulonglong2* xu2 = (const ulonglong2*)xs2;

    // ---- GEMM: cols (cA, cA+32) of head t>>5, graphs packed in f32x2 ----
    ull aA[NN], aB[NN];
    #pragma unroll
    for (int n = 0; n < NN; n++) { aA[n] = 0ull; aB[n] = 0ull; }

    #pragma unroll 2
    for (int ks = 0; ks < K/4; ks++) {
        float4 f1 = Wp[ks*256 + t];
        float4 f2 = Wp[ks*256 + 128 + t];
        ull w0A = pk2(f1.x, f1.x), w0B = pk2(f1.y, f1.y);
        ull w1A = pk2(f1.z, f1.z), w1B = pk2(f1.w, f1.w);
        ull w2A = pk2(f2.x, f2.x), w2B = pk2(f2.y, f2.y);
        ull w3A = pk2(f2.z, f2.z), w3B = pk2(f2.w, f2.w);
        #pragma unroll
        for (int n = 0; n < NN; n++) {
            ulonglong2 x01 = xu2[n*S2 + 2*ks];
            ulonglong2 x23 = xu2[n*S2 + 2*ks + 1];
            ull a = aA[n];
            a = fma2(w0A, x01.x, a);
            a = fma2(w1A, x01.y, a);
            a = fma2(w2A, x23.x, a);
            a = fma2(w3A, x23.y, a);
            aA[n] = a;
            ull b = aB[n];
            b = fma2(w0B, x01.x, b);
            b = fma2(w1B, x01.y, b);
            b = fma2(w2B, x23.x, b);
            b = fma2(w3B, x23.y, b);
            aB[n] = b;
        }
    }

    // ---- attention logits (both graphs packed): aljp[n*8+j] ----
    if (t < NN * 8) {
        int n = t >> 3, j = t & 7;
        const float4* wa = (const float4*)(waSD + j*K);
        ull s0 = 0ull, s1 = 0ull, s2 = 0ull, s3 = 0ull;
        #pragma unroll 4
        for (int q = 0; q < K/4; q++) {
            float4 w = wa[q];
            ulonglong2 xa = xu2[n*S2 + 2*q];
            ulonglong2 xb = xu2[n*S2 + 2*q + 1];
            s0 = fma2(xa.x, pk2(w.x, w.x), s0);
            s1 = fma2(xa.y, pk2(w.y, w.y), s1);
            s2 = fma2(xb.x, pk2(w.z, w.z), s2);
            s3 = fma2(xb.y, pk2(w.w, w.w), s3);
        }
        aljp[n*8 + j] = add2(add2(s0, s1), add2(s2, s3));
    }
    __syncthreads();

    // ---- fused exp + normalized attention build: Mpk[h][d][s] (g0,g1) ----
    if (t < 2*NN*NH) {
        int g = t / (NN*NH), r = t - g*(NN*NH);
        int d = r >> 2, hh = r & 3;
        float* Mrow = (float*)Mpk + ((hh*NN + d)*NN)*2 + g;
        const float* aljf = (const float*)aljp;
        float ad = aljf[(d*8 + 4 + hh)*2 + g];
        float dn = 0.f;
        int e1 = off[g][d+1];
        for (int e = off[g][d]; e < e1; e++) {
            int s = srcS[g][e];
            float v = aljf[(s*8 + hh)*2 + g] + ad;
            v = (v > 0.f) ? v : NEG * v;
            float ex = __expf(v);
            Mrow[s*2] += ex;
            dn += ex;
        }
        float inv = __fdividef(1.f, dn);
        #pragma unroll
        for (int s = 0; s < NN; s++) Mrow[s*2] *= inv;
    }
    __syncthreads();

    // ---- aggregation in registers: one M broadcast feeds both columns ----
    {
        const ull* Mp = Mpk + (t >> 5)*(NN*NN);
        int colA = ((t >> 5) << 6) + (t & 31);
        #pragma unroll
        for (int n = 0; n < NN; n++) {
            ull gA = 0ull, gB = 0ull;
            #pragma unroll
            for (int s = 0; s < NN; s++) {
                ull m = Mp[n*NN + s];
                gA = fma2(m, aA[s], gA);
                gB = fma2(m, aB[s], gB);
            }
            hs2[n*NO + colA]      = gA;
            hs2[n*NO + colA + 32] = gB;
        }
    }
    __syncthreads();

    // ---- head mean + bias (+relu) -> xs2 (ull stride 66) ----
    const ull quart = pk2(0.25f, 0.25f);
    for (int i = t; i < NN*NC; i += NT) {
        int n = i >> 6, c = i & 63;
        ull v = add2(add2(hs2[n*NO + c],       hs2[n*NO + 64 + c]),
                     add2(hs2[n*NO + 128 + c], hs2[n*NO + 192 + c]));
        float bb = bias[c];
        v = fma2(v, quart, pk2(bb, bb));
        if (RELU) {
            float x, y; upk2(v, x, y);
            v = pk2(fmaxf(x, 0.f), fmaxf(y, 0.f));
        }
        xs2[n*66 + c] = v;
    }
    __syncthreads();
}

__global__ void __launch_bounds__(NT, 3)
gat_kernel(const float* __restrict__ feature, const int* __restrict__ eraw,
           const float* __restrict__ b1v, const float* __restrict__ b2v,
           float* __restrict__ out, int B, int E)
{
    __shared__ __align__(16) ull xs2[NN*130];    // paired features / layer IO
    __shared__ __align__(16) ull hs2[NN*NO];     // paired aggregated columns
    __shared__ __align__(16) ull Mpk[NH*NN*NN];  // paired normalized attention
    __shared__ ull   aljp[NN*8];
    __shared__ int   srcS[2][MAXE];
    __shared__ int   cnt[2][NN], off[2][NN+1];
    __shared__ float2 red[4];

    const int t = threadIdx.x;
    const int lane = t & 31, warp = t >> 5;
    const int g0 = 2*blockIdx.x;
    const int g1 = (g0 + 1 < B) ? g0 + 1 : g0;
    const int NE = E + NN;
    const int is64 = g_is64;

    if (t < NN) { cnt[0][t] = 0; cnt[1][t] = 0; }

    // load + interleave features of both graphs
    {
        const float4* xg0 = (const float4*)(feature + (size_t)g0 * NN * FIN);
        const float4* xg1 = (const float4*)(feature + (size_t)g1 * NN * FIN);
        ulonglong2* xo = (ulonglong2*)xs2;
        for (int i = t; i < NN*FIN/4; i += NT) {
            int n = i >> 5, k4 = i & 31;
            float4 a0 = xg0[n*32 + k4];
            float4 a1 = xg1[n*32 + k4];
            ulonglong2 v0, v1;
            v0.x = pk2(a0.x, a1.x); v0.y = pk2(a0.y, a1.y);
            v1.x = pk2(a0.z, a1.z); v1.y = pk2(a0.w, a1.w);
            xo[n*65 + 2*k4]     = v0;
            xo[n*65 + 2*k4 + 1] = v1;
        }
    }
    __syncthreads();

    // ---- counting sort (src only; dst is implicit in the bucket) ----
    #pragma unroll
    for (int g = 0; g < 2; g++) {
        int bg = g ? g1 : g0;
        for (int e = t; e < NE; e += NT) {
            int d;
            if (e < E) {
                size_t base = ((size_t)bg * E + e) * 2;
                d = is64 ? (int)((const long long*)eraw)[base + 1] : eraw[base + 1];
            } else d = e - E;
            atomicAdd(&cnt[g][d], 1);
        }
    }
    __syncthreads();
    if (t < 2) {
        int s = 0;
        #pragma unroll
        for (int i = 0; i < NN; i++) { off[t][i] = s; s += cnt[t][i]; cnt[t][i] = off[t][i]; }
        off[t][NN] = s;
    }
    __syncthreads();
    #pragma unroll
    for (int g = 0; g < 2; g++) {
        int bg = g ? g1 : g0;
        for (int e = t; e < NE; e += NT) {
            int s, d;
            if (e < E) {
                size_t base = ((size_t)bg * E + e) * 2;
                if (is64) { const long long* p = (const long long*)eraw;
                            s = (int)p[base]; d = (int)p[base + 1]; }
                else      { s = eraw[base];   d = eraw[base + 1]; }
            } else { s = d = e - E; }
            int pos = atomicAdd(&cnt[g][d], 1);
            srcS[g][pos] = s;
        }
    }
    __syncthreads();

    gat_layer<FIN, 65, true >(g_Wp1, g_waSD1, b1v, xs2, hs2, Mpk, aljp,
                              srcS, off, t);
    gat_layer<NC,  33, false>(g_Wp2, g_waSD2, b2v, xs2, hs2, Mpk, aljp,
                              srcS, off, t);

    // ---- fused head: both graphs at once ----
    ull pp = 0ull;
    for (int i = t; i < NN*NC; i += NT) {
        int n = i >> 6, c = i & 63;
        float w = g_wfused[i];
        pp = fma2(xs2[n*66 + c], pk2(w, w), pp);
    }
    float px, py; upk2(pp, px, py);
    #pragma unroll
    for (int o = 16; o; o >>= 1) {
        px += __shfl_xor_sync(0xffffffffu, px, o);
        py += __shfl_xor_sync(0xffffffffu, py, o);
    }
    if (lane == 0) red[warp] = make_float2(px, py);
    __syncthreads();
    if (t == 0) {
        float sx = g_bfused, sy = g_bfused;
        #pragma unroll
        for (int w = 0; w < 4; w++) { sx += red[w].x; sy += red[w].y; }
        out[g0] = 1.f / (1.f + __expf(-sx));
        out[g1] = 1.f / (1.f + __expf(-sy));
    }
}

extern "C" void kernel_launch(void* const* d_in, const int* in_sizes, int n_in,
                              void* d_out, int out_size)
{
    const float* feature = (const float*)d_in[0];
    const int*   edges   = (const int*)  d_in[1];
    const float* W1   = (const float*)d_in[2];
    const float* as1  = (const float*)d_in[3];
    const float* ad1  = (const float*)d_in[4];
    const float* b1   = (const float*)d_in[5];
    const float* W2   = (const float*)d_in[6];
    const float* as2  = (const float*)d_in[7];
    const float* ad2  = (const float*)d_in[8];
    const float* b2   = (const float*)d_in[9];
    const float* Wlin = (const float*)d_in[10];
    const float* blin = (const float*)d_in[11];
    const float* Wpred= (const float*)d_in[12];
    const float* bpred= (const float*)d_in[13];

    int B = in_sizes[0] / (NN * FIN);       // 16384
    int E = in_sizes[1] / (2 * B);          // 182

    prep_kernel<<<48, 256>>>(W1, as1, ad1, W2, as2, ad2,
                             Wlin, blin, Wpred, bpred, edges);
    int Bp = (B + 1) / 2;
    gat_kernel<<<Bp, NT>>>(feature, edges, b1, b2, (float*)d_out, B, E);
}

// round 8
// speedup vs baseline: 2.4931x; 1.1553x over previous
#include <cuda_runtime.h>

#define NN 14      // nodes per graph
#define NH 4       // heads
#define NC 64      // per-head channels
#define NO 256     // NH*NC
#define FIN 128
#define NEG 0.2f
#define MAXE 224   // >= E + NN = 196
#define NTP 64     // threads per graph-pair (2 warps)
#define NPAIR 2    // pairs per CTA
#define NT (NTP*NPAIR)

typedef unsigned long long ull;

__device__ __forceinline__ ull pk2(float x, float y) {
    ull r; asm("mov.b64 %0, {%1, %2};" : "=l"(r) : "f"(x), "f"(y)); return r;
}
__device__ __forceinline__ void upk2(ull v, float& x, float& y) {
    asm("mov.b64 {%0, %1}, %2;" : "=f"(x), "=f"(y) : "l"(v));
}
__device__ __forceinline__ ull fma2(ull a, ull b, ull c) {
    ull d; asm("fma.rn.f32x2 %0, %1, %2, %3;" : "=l"(d) : "l"(a), "l"(b), "l"(c)); return d;
}
__device__ __forceinline__ ull add2(ull a, ull b) {
    ull d; asm("add.rn.f32x2 %0, %1, %2;" : "=l"(d) : "l"(a), "l"(b)); return d;
}
__device__ __forceinline__ void barp(int id) {
    asm volatile("bar.sync %0, %1;" :: "r"(id), "r"(NTP) : "memory");
}

// ---- precomputed weights ----
// Thread td (0..63) of a pair: w=td>>5, lane=td&31, h=2w+(lane>>4), cc=lane&15,
// owns cols c_j = h*64 + cc + 16j (j=0..3).
// g_Wq[(ks2*64+td)*2+m] = (W[2ks2][c_{2m}], W[2ks2][c_{2m+1}],
//                          W[2ks2+1][c_{2m}], W[2ks2+1][c_{2m+1}])
__device__ float4 g_W1q[64 * 64 * 2];
__device__ float4 g_W2q[32 * 64 * 2];
__device__ float  g_wfused[NN * NC];   // W_lin @ W_pred
__device__ float  g_bfused;
__device__ int    g_is64;

__global__ void prep_kernel(const float* __restrict__ W1, const float* __restrict__ W2,
                            const float* __restrict__ Wlin, const float* __restrict__ blin,
                            const float* __restrict__ Wpred, const float* __restrict__ bpred,
                            const int* __restrict__ edges)
{
    int tid = blockIdx.x * blockDim.x + threadIdx.x;
    int nt  = gridDim.x * blockDim.x;

    for (int i = tid; i < 64*64*2; i += nt) {
        int ks2 = i >> 7, r = i & 127, td = r >> 1, m = r & 1;
        int w = td >> 5, lane = td & 31;
        int h = 2*w + (lane >> 4), cc = lane & 15;
        int c0 = h*64 + cc + 32*m, c1 = c0 + 16;
        g_W1q[i] = make_float4(W1[(2*ks2)*NO + c0],   W1[(2*ks2)*NO + c1],
                               W1[(2*ks2+1)*NO + c0], W1[(2*ks2+1)*NO + c1]);
    }
    for (int i = tid; i < 32*64*2; i += nt) {
        int ks2 = i >> 7, r = i & 127, td = r >> 1, m = r & 1;
        int w = td >> 5, lane = td & 31;
        int h = 2*w + (lane >> 4), cc = lane & 15;
        int c0 = h*64 + cc + 32*m, c1 = c0 + 16;
        g_W2q[i] = make_float4(W2[(2*ks2)*NO + c0],   W2[(2*ks2)*NO + c1],
                               W2[(2*ks2+1)*NO + c0], W2[(2*ks2+1)*NO + c1]);
    }
    for (int i = tid; i < NN * NC; i += nt) {
        float s = 0.f;
        #pragma unroll
        for (int j = 0; j < NC/2; j++) s = fmaf(Wlin[i*(NC/2) + j], Wpred[j], s);
        g_wfused[i] = s;
    }
    if (tid == 0) {
        float s = bpred[0];
        #pragma unroll
        for (int j = 0; j < NC/2; j++) s = fmaf(blin[j], Wpred[j], s);
        g_bfused = s;
        int any = 0;
        #pragma unroll
        for (int k = 1; k < 256; k += 2) any |= edges[k];
        g_is64 = (any == 0) ? 1 : 0;
    }
}

// Per-pair shared state. xs2 also hosts warp1's head-mean partial at [928, 1824).
// __align__(16): sizeof must round to 16 so psm[1] keeps 16-B alignment for
// the ulonglong2 (128-bit) accesses — this was the round-7 misaligned-address bug.
struct __align__(16) PairSmem {
    ull  xs2[1832];           // layer input (stride 130 ull) / output (stride 66)
    ull  Mpk[NH*NN*NN];       // 784: paired normalized attention
    ull  part0[NN*64];        // 896: warp0 head-partial
    ull  aljp[NN*8];          // paired attention logits
    int  srcS[2][MAXE];
    int  cnt[2][NN];
    int  off[2][NN+1];
    float2 red[2];
};

// One GAT layer for a graph pair (2 warps). acc kept in registers throughout.
template<int K, int S2, bool RELU>
__device__ __forceinline__ void gat_layer(
    const float4* __restrict__ Wq,
    const float* __restrict__ a_s, const float* __restrict__ a_d,
    const float* __restrict__ bias,
    PairSmem* ps, int td, int lane, int w, int h, int cc, int barid)
{
    // zero paired attention matrix (M-build happens after next barrier)
    for (int i = td; i < NH*NN*NN; i += NTP) ps->Mpk[i] = 0ull;

    const ulonglong2* xu2 = (const ulonglong2*)ps->xs2;

    // per-thread attention vector slices
    float asv[4], adv[4];
    #pragma unroll
    for (int j = 0; j < 4; j++) {
        asv[j] = a_s[h*NC + cc + 16*j];
        adv[j] = a_d[h*NC + cc + 16*j];
    }

    // ---- GEMM: 4 columns per thread, graphs packed in f32x2 ----
    ull acc[NN][4];
    #pragma unroll
    for (int n = 0; n < NN; n++)
        #pragma unroll
        for (int j = 0; j < 4; j++) acc[n][j] = 0ull;

    #pragma unroll 2
    for (int ks2 = 0; ks2 < K/2; ks2++) {
        float4 F0 = Wq[(ks2*64 + td)*2 + 0];
        float4 F1 = Wq[(ks2*64 + td)*2 + 1];
        ull w00 = pk2(F0.x, F0.x), w01 = pk2(F0.y, F0.y);
        ull w02 = pk2(F0.z, F0.z), w03 = pk2(F0.w, F0.w);
        ull w10 = pk2(F1.x, F1.x), w11 = pk2(F1.y, F1.y);
        ull w12 = pk2(F1.z, F1.z), w13 = pk2(F1.w, F1.w);
        #pragma unroll
        for (int n = 0; n < NN; n++) {
            ulonglong2 x = xu2[n*S2 + ks2];
            acc[n][0] = fma2(w00, x.x, acc[n][0]);
            acc[n][0] = fma2(w02, x.y, acc[n][0]);
            acc[n][1] = fma2(w01, x.x, acc[n][1]);
            acc[n][1] = fma2(w03, x.y, acc[n][1]);
            acc[n][2] = fma2(w10, x.x, acc[n][2]);
            acc[n][2] = fma2(w12, x.y, acc[n][2]);
            acc[n][3] = fma2(w11, x.x, acc[n][3]);
            acc[n][3] = fma2(w13, x.y, acc[n][3]);
        }
    }

    // ---- attention logits from accumulators + 16-lane shfl reduce ----
    #pragma unroll
    for (int n = 0; n < NN; n++) {
        ull ss = 0ull, sd = 0ull;
        #pragma unroll
        for (int j = 0; j < 4; j++) {
            ss = fma2(acc[n][j], pk2(asv[j], asv[j]), ss);
            sd = fma2(acc[n][j], pk2(adv[j], adv[j]), sd);
        }
        #pragma unroll
        for (int o = 1; o < 16; o <<= 1) {
            ss = add2(ss, __shfl_xor_sync(0xffffffffu, ss, o));
            sd = add2(sd, __shfl_xor_sync(0xffffffffu, sd, o));
        }
        if ((lane & 15) == 0) {
            ps->aljp[n*8 + h]     = ss;
            ps->aljp[n*8 + 4 + h] = sd;
        }
    }
    barp(barid);

    // ---- fused exp + normalized attention build: Mpk[h][d][s] (g0,g1) ----
    for (int idx = td; idx < 2*NN*NH; idx += NTP) {
        int g = idx / (NN*NH), r = idx - g*(NN*NH);
        int d = r >> 2, hh = r & 3;
        float* Mrow = (float*)ps->Mpk + ((hh*NN + d)*NN)*2 + g;
        const float* aljf = (const float*)ps->aljp;
        float ad = aljf[(d*8 + 4 + hh)*2 + g];
        float dn = 0.f;
        int e1 = ps->off[g][d+1];
        for (int e = ps->off[g][d]; e < e1; e++) {
            int s = ps->srcS[g][e];
            float v = aljf[(s*8 + hh)*2 + g] + ad;
            v = (v > 0.f) ? v : NEG * v;
            float ex = __expf(v);
            Mrow[s*2] += ex;
            dn += ex;
        }
        float inv = __fdividef(1.f, dn);
        #pragma unroll
        for (int s = 0; s < NN; s++) Mrow[s*2] *= inv;
    }
    barp(barid);

    // ---- aggregation in registers, head-pair fold via shfl(16) ----
    {
        ull* part = w ? (ps->xs2 + 928) : ps->part0;
        const ull* Mp = ps->Mpk + h*(NN*NN);
        #pragma unroll
        for (int n = 0; n < NN; n++) {
            ull g0 = 0ull, g1 = 0ull, g2 = 0ull, g3 = 0ull;
            #pragma unroll
            for (int s = 0; s < NN; s++) {
                ull m = Mp[n*NN + s];
                g0 = fma2(m, acc[s][0], g0);
                g1 = fma2(m, acc[s][1], g1);
                g2 = fma2(m, acc[s][2], g2);
                g3 = fma2(m, acc[s][3], g3);
            }
            g0 = add2(g0, __shfl_xor_sync(0xffffffffu, g0, 16));
            g1 = add2(g1, __shfl_xor_sync(0xffffffffu, g1, 16));
            g2 = add2(g2, __shfl_xor_sync(0xffffffffu, g2, 16));
            g3 = add2(g3, __shfl_xor_sync(0xffffffffu, g3, 16));
            if (lane < 16) {
                part[n*64 + cc]      = g0;
                part[n*64 + cc + 16] = g1;
                part[n*64 + cc + 32] = g2;
                part[n*64 + cc + 48] = g3;
            }
        }
    }
    barp(barid);

    // ---- head mean + bias (+relu) -> xs2 (ull stride 66) ----
    const ull quart = pk2(0.25f, 0.25f);
    const ull* p1 = ps->xs2 + 928;
    for (int i = td; i < NN*NC; i += NTP) {
        int n = i >> 6, c = i & 63;
        ull v = add2(ps->part0[i], p1[i]);
        float bb = bias[c];
        v = fma2(v, quart, pk2(bb, bb));
        if (RELU) {
            float x, y; upk2(v, x, y);
            v = pk2(fmaxf(x, 0.f), fmaxf(y, 0.f));
        }
        ps->xs2[n*66 + c] = v;
    }
    barp(barid);
}

__global__ void __launch_bounds__(NT, 3)
gat_kernel(const float* __restrict__ feature, const int* __restrict__ eraw,
           const float* __restrict__ as1, const float* __restrict__ ad1,
           const float* __restrict__ b1v,
           const float* __restrict__ as2, const float* __restrict__ ad2,
           const float* __restrict__ b2v,
           float* __restrict__ out, int B, int E)
{
    __shared__ __align__(16) PairSmem psm[NPAIR];

    const int t = threadIdx.x;
    const int pair = t / NTP;
    const int td = t - pair * NTP;
    const int lane = td & 31, w = td >> 5;
    const int h = 2*w + (lane >> 4), cc = lane & 15;
    const int barid = pair + 1;

    PairSmem* ps = &psm[pair];

    const int pidx = blockIdx.x * NPAIR + pair;
    const int g0 = 2*pidx;
    if (g0 >= B) return;
    const int g1 = (g0 + 1 < B) ? g0 + 1 : g0;
    const int NE = E + NN;
    const int is64 = g_is64;

    if (td < NN) { ps->cnt[0][td] = 0; ps->cnt[1][td] = 0; }

    // load + interleave features of both graphs (stride 65 ulonglong2)
    {
        const float4* xg0 = (const float4*)(feature + (size_t)g0 * NN * FIN);
        const float4* xg1 = (const float4*)(feature + (size_t)g1 * NN * FIN);
        ulonglong2* xo = (ulonglong2*)ps->xs2;
        for (int i = td; i < NN*FIN/4; i += NTP) {
            int n = i >> 5, k4 = i & 31;
            float4 a0 = xg0[n*32 + k4];
            float4 a1 = xg1[n*32 + k4];
            ulonglong2 v0, v1;
            v0.x = pk2(a0.x, a1.x); v0.y = pk2(a0.y, a1.y);
            v1.x = pk2(a0.z, a1.z); v1.y = pk2(a0.w, a1.w);
            xo[n*65 + 2*k4]     = v0;
            xo[n*65 + 2*k4 + 1] = v1;
        }
    }
    barp(barid);

    // ---- counting sort of both graphs' edges by dst (src kept) ----
    #pragma unroll
    for (int g = 0; g < 2; g++) {
        int bg = g ? g1 : g0;
        for (int e = td; e < NE; e += NTP) {
            int d;
            if (e < E) {
                size_t base = ((size_t)bg * E + e) * 2;
                d = is64 ? (int)((const long long*)eraw)[base + 1] : eraw[base + 1];
            } else d = e - E;
            atomicAdd(&ps->cnt[g][d], 1);
        }
    }
    barp(barid);
    if (td < 2) {
        int s = 0;
        #pragma unroll
        for (int i = 0; i < NN; i++) {
            ps->off[td][i] = s; s += ps->cnt[td][i]; ps->cnt[td][i] = ps->off[td][i];
        }
        ps->off[td][NN] = s;
    }
    barp(barid);
    #pragma unroll
    for (int g = 0; g < 2; g++) {
        int bg = g ? g1 : g0;
        for (int e = td; e < NE; e += NTP) {
            int s, d;
            if (e < E) {
                size_t base = ((size_t)bg * E + e) * 2;
                if (is64) { const long long* p = (const long long*)eraw;
                            s = (int)p[base]; d = (int)p[base + 1]; }
                else      { s = eraw[base];   d = eraw[base + 1]; }
            } else { s = d = e - E; }
            int pos = atomicAdd(&ps->cnt[g][d], 1);
            ps->srcS[g][pos] = s;
        }
    }
    barp(barid);

    gat_layer<FIN, 65, true >(g_W1q, as1, ad1, b1v, ps, td, lane, w, h, cc, barid);
    gat_layer<NC,  33, false>(g_W2q, as2, ad2, b2v, ps, td, lane, w, h, cc, barid);

    // ---- fused head: both graphs at once ----
    ull pp = 0ull;
    for (int i = td; i < NN*NC; i += NTP) {
        int n = i >> 6, c = i & 63;
        float wv = g_wfused[i];
        pp = fma2(ps->xs2[n*66 + c], pk2(wv, wv), pp);
    }
    float px, py; upk2(pp, px, py);
    #pragma unroll
    for (int o = 16; o; o >>= 1) {
        px += __shfl_xor_sync(0xffffffffu, px, o);
        py += __shfl_xor_sync(0xffffffffu, py, o);
    }
    if (lane == 0) ps->red[w] = make_float2(px, py);
    barp(barid);
    if (td == 0) {
        float sx = g_bfused + ps->red[0].x + ps->red[1].x;
        float sy = g_bfused + ps->red[0].y + ps->red[1].y;
        out[g0] = 1.f / (1.f + __expf(-sx));
        out[g1] = 1.f / (1.f + __expf(-sy));
    }
}

extern "C" void kernel_launch(void* const* d_in, const int* in_sizes, int n_in,
                              void* d_out, int out_size)
{
    const float* feature = (const float*)d_in[0];
    const int*   edges   = (const int*)  d_in[1];
    const float* W1   = (const float*)d_in[2];
    const float* as1  = (const float*)d_in[3];
    const float* ad1  = (const float*)d_in[4];
    const float* b1   = (const float*)d_in[5];
    const float* W2   = (const float*)d_in[6];
    const float* as2  = (const float*)d_in[7];
    const float* ad2  = (const float*)d_in[8];
    const float* b2   = (const float*)d_in[9];
    const float* Wlin = (const float*)d_in[10];
    const float* blin = (const float*)d_in[11];
    const float* Wpred= (const float*)d_in[12];
    const float* bpred= (const float*)d_in[13];

    int B = in_sizes[0] / (NN * FIN);       // 16384
    int E = in_sizes[1] / (2 * B);          // 182

    prep_kernel<<<48, 256>>>(W1, W2, Wlin, blin, Wpred, bpred, edges);
    int nPairs = (B + 1) / 2;
    int grid = (nPairs + NPAIR - 1) / NPAIR;
    gat_kernel<<<grid, NT>>>(feature, edges, as1, ad1, b1,
                             as2, ad2, b2, (float*)d_out, B, E);
}

// round 9
// speedup vs baseline: 2.5883x; 1.0382x over previous
#include <cuda_runtime.h>

#define NN 14      // nodes per graph
#define NH 4       // heads
#define NC 64      // per-head channels
#define NO 256     // NH*NC
#define FIN 128
#define NEG 0.2f
#define MAXE 200   // >= E + NN = 196
#define NTP 64     // threads per graph-pair (2 warps)
#define NPAIR 2    // pairs per CTA
#define NT (NTP*NPAIR)

typedef unsigned long long ull;

__device__ __forceinline__ ull pk2(float x, float y) {
    ull r; asm("mov.b64 %0, {%1, %2};" : "=l"(r) : "f"(x), "f"(y)); return r;
}
__device__ __forceinline__ void upk2(ull v, float& x, float& y) {
    asm("mov.b64 {%0, %1}, %2;" : "=f"(x), "=f"(y) : "l"(v));
}
__device__ __forceinline__ ull fma2(ull a, ull b, ull c) {
    ull d; asm("fma.rn.f32x2 %0, %1, %2, %3;" : "=l"(d) : "l"(a), "l"(b), "l"(c)); return d;
}
__device__ __forceinline__ ull add2(ull a, ull b) {
    ull d; asm("add.rn.f32x2 %0, %1, %2;" : "=l"(d) : "l"(a), "l"(b)); return d;
}
__device__ __forceinline__ void barp(int id) {
    asm volatile("bar.sync %0, %1;" :: "r"(id), "r"(NTP) : "memory");
}

// ---- precomputed weights ----
// Thread td (0..63): w=td>>5, lane=td&31, h=2w+(lane>>4), cc=lane&15,
// owns cols c_j = h*64 + cc + 16j (j=0..3).
__device__ float4 g_W1q[64 * 64 * 2];
__device__ float4 g_W2q[32 * 64 * 2];
__device__ float  g_wfused[NN * NC];   // W_lin @ W_pred
__device__ float  g_bfused;
__device__ int    g_is64;

__global__ void prep_kernel(const float* __restrict__ W1, const float* __restrict__ W2,
                            const float* __restrict__ Wlin, const float* __restrict__ blin,
                            const float* __restrict__ Wpred, const float* __restrict__ bpred,
                            const int* __restrict__ edges)
{
    int tid = blockIdx.x * blockDim.x + threadIdx.x;
    int nt  = gridDim.x * blockDim.x;

    for (int i = tid; i < 64*64*2; i += nt) {
        int ks2 = i >> 7, r = i & 127, td = r >> 1, m = r & 1;
        int w = td >> 5, lane = td & 31;
        int h = 2*w + (lane >> 4), cc = lane & 15;
        int c0 = h*64 + cc + 32*m, c1 = c0 + 16;
        g_W1q[i] = make_float4(W1[(2*ks2)*NO + c0],   W1[(2*ks2)*NO + c1],
                               W1[(2*ks2+1)*NO + c0], W1[(2*ks2+1)*NO + c1]);
    }
    for (int i = tid; i < 32*64*2; i += nt) {
        int ks2 = i >> 7, r = i & 127, td = r >> 1, m = r & 1;
        int w = td >> 5, lane = td & 31;
        int h = 2*w + (lane >> 4), cc = lane & 15;
        int c0 = h*64 + cc + 32*m, c1 = c0 + 16;
        g_W2q[i] = make_float4(W2[(2*ks2)*NO + c0],   W2[(2*ks2)*NO + c1],
                               W2[(2*ks2+1)*NO + c0], W2[(2*ks2+1)*NO + c1]);
    }
    for (int i = tid; i < NN * NC; i += nt) {
        float s = 0.f;
        #pragma unroll
        for (int j = 0; j < NC/2; j++) s = fmaf(Wlin[i*(NC/2) + j], Wpred[j], s);
        g_wfused[i] = s;
    }
    if (tid == 0) {
        float s = bpred[0];
        #pragma unroll
        for (int j = 0; j < NC/2; j++) s = fmaf(blin[j], Wpred[j], s);
        g_bfused = s;
        int any = 0;
        #pragma unroll
        for (int k = 1; k < 256; k += 2) any |= edges[k];
        g_is64 = (any == 0) ? 1 : 0;
    }
}

// Per-pair shared state. Separate part0/part1 so the two warps' phases can
// drift without aliasing xs2 (warp-local pipeline). srcS as uint8 (ids < 14).
struct __align__(16) PairSmem {
    ull  xs2[1820];           // layer input (u2 stride 65) / output (ull stride 66)
    ull  Mpk[NH*NN*NN];       // 784: paired normalized attention (per-warp halves)
    ull  part0[NN*64];        // warp0 head-partial
    ull  part1[NN*64];        // warp1 head-partial
    ull  aljp[NN*8];          // paired attention logits
    unsigned char srcS[2][MAXE];
    int  cnt[2][NN];
    int  off[2][NN+1];
    float2 red[2];
};

// One GAT layer for a graph pair. Warp-local except the head-mean combine.
template<int K, int S2, bool RELU>
__device__ __forceinline__ void gat_layer(
    const float4* __restrict__ Wq,
    const float* __restrict__ a_s, const float* __restrict__ a_d,
    const float* __restrict__ bias,
    PairSmem* ps, int td, int lane, int w, int h, int cc, int barid)
{
    // zero THIS warp's Mpk half (heads 2w, 2w+1) — warp-private region
    {
        ull* Mhalf = ps->Mpk + w*392;
        for (int i = lane; i < 392; i += 32) Mhalf[i] = 0ull;
    }

    const ulonglong2* xu2 = (const ulonglong2*)ps->xs2;

    float asv[4], adv[4];
    #pragma unroll
    for (int j = 0; j < 4; j++) {
        asv[j] = a_s[h*NC + cc + 16*j];
        adv[j] = a_d[h*NC + cc + 16*j];
    }

    // ---- GEMM: 4 columns per thread, graphs packed in f32x2 ----
    ull acc[NN][4];
    #pragma unroll
    for (int n = 0; n < NN; n++)
        #pragma unroll
        for (int j = 0; j < 4; j++) acc[n][j] = 0ull;

    #pragma unroll 2
    for (int ks2 = 0; ks2 < K/2; ks2++) {
        float4 F0 = Wq[(ks2*64 + td)*2 + 0];
        float4 F1 = Wq[(ks2*64 + td)*2 + 1];
        ull w00 = pk2(F0.x, F0.x), w01 = pk2(F0.y, F0.y);
        ull w02 = pk2(F0.z, F0.z), w03 = pk2(F0.w, F0.w);
        ull w10 = pk2(F1.x, F1.x), w11 = pk2(F1.y, F1.y);
        ull w12 = pk2(F1.z, F1.z), w13 = pk2(F1.w, F1.w);
        #pragma unroll
        for (int n = 0; n < NN; n++) {
            ulonglong2 x = xu2[n*S2 + ks2];
            acc[n][0] = fma2(w00, x.x, acc[n][0]);
            acc[n][0] = fma2(w02, x.y, acc[n][0]);
            acc[n][1] = fma2(w01, x.x, acc[n][1]);
            acc[n][1] = fma2(w03, x.y, acc[n][1]);
            acc[n][2] = fma2(w10, x.x, acc[n][2]);
            acc[n][2] = fma2(w12, x.y, acc[n][2]);
            acc[n][3] = fma2(w11, x.x, acc[n][3]);
            acc[n][3] = fma2(w13, x.y, acc[n][3]);
        }
    }

    // ---- attention logits: in-register dot + 16-lane shfl reduce ----
    #pragma unroll
    for (int n = 0; n < NN; n++) {
        ull ss = 0ull, sd = 0ull;
        #pragma unroll
        for (int j = 0; j < 4; j++) {
            ss = fma2(acc[n][j], pk2(asv[j], asv[j]), ss);
            sd = fma2(acc[n][j], pk2(adv[j], adv[j]), sd);
        }
        #pragma unroll
        for (int o = 1; o < 16; o <<= 1) {
            ss = add2(ss, __shfl_xor_sync(0xffffffffu, ss, o));
            sd = add2(sd, __shfl_xor_sync(0xffffffffu, sd, o));
        }
        if ((lane & 15) == 0) {
            ps->aljp[n*8 + h]     = ss;
            ps->aljp[n*8 + 4 + h] = sd;
        }
    }
    __syncwarp();

    // ---- M-build for THIS warp's heads only: 56 tasks = (g, d, hsub) ----
    {
        const float* aljf = (const float*)ps->aljp;
        for (int idx = lane; idx < 56; idx += 32) {
            int g = idx / 28;
            int r = idx - g*28;
            int d = r >> 1;
            int hh = 2*w + (r & 1);
            float* Mrow = (float*)ps->Mpk + ((hh*NN + d)*NN)*2 + g;
            float ad = aljf[(d*8 + 4 + hh)*2 + g];
            float dn = 0.f;
            int e1 = ps->off[g][d+1];
            for (int e = ps->off[g][d]; e < e1; e++) {
                int s = ps->srcS[g][e];
                float v = aljf[(s*8 + hh)*2 + g] + ad;
                v = (v > 0.f) ? v : NEG * v;
                float ex = __expf(v);
                Mrow[s*2] += ex;
                dn += ex;
            }
            float inv = __fdividef(1.f, dn);
            #pragma unroll
            for (int s = 0; s < NN; s++) Mrow[s*2] *= inv;
        }
    }
    __syncwarp();

    // ---- aggregation in registers (own heads), head-pair fold via shfl(16) ----
    {
        ull* part = w ? ps->part1 : ps->part0;
        const ull* Mp = ps->Mpk + h*(NN*NN);
        #pragma unroll
        for (int n = 0; n < NN; n++) {
            ull g0 = 0ull, g1 = 0ull, g2 = 0ull, g3 = 0ull;
            #pragma unroll
            for (int s = 0; s < NN; s++) {
                ull m = Mp[n*NN + s];
                g0 = fma2(m, acc[s][0], g0);
                g1 = fma2(m, acc[s][1], g1);
                g2 = fma2(m, acc[s][2], g2);
                g3 = fma2(m, acc[s][3], g3);
            }
            g0 = add2(g0, __shfl_xor_sync(0xffffffffu, g0, 16));
            g1 = add2(g1, __shfl_xor_sync(0xffffffffu, g1, 16));
            g2 = add2(g2, __shfl_xor_sync(0xffffffffu, g2, 16));
            g3 = add2(g3, __shfl_xor_sync(0xffffffffu, g3, 16));
            if (lane < 16) {
                part[n*64 + cc]      = g0;
                part[n*64 + cc + 16] = g1;
                part[n*64 + cc + 32] = g2;
                part[n*64 + cc + 48] = g3;
            }
        }
    }
    barp(barid);   // both warps' partials ready

    // ---- head mean + bias (+relu) -> xs2 (ull stride 66) ----
    const ull quart = pk2(0.25f, 0.25f);
    for (int i = td; i < NN*NC; i += NTP) {
        int n = i >> 6, c = i & 63;
        ull v = add2(ps->part0[i], ps->part1[i]);
        float bb = bias[c];
        v = fma2(v, quart, pk2(bb, bb));
        if (RELU) {
            float x, y; upk2(v, x, y);
            v = pk2(fmaxf(x, 0.f), fmaxf(y, 0.f));
        }
        ps->xs2[n*66 + c] = v;
    }
    barp(barid);   // xs2 ready for next consumer
}

__global__ void __launch_bounds__(NT, 3)
gat_kernel(const float* __restrict__ feature, const int* __restrict__ eraw,
           const float* __restrict__ as1, const float* __restrict__ ad1,
           const float* __restrict__ b1v,
           const float* __restrict__ as2, const float* __restrict__ ad2,
           const float* __restrict__ b2v,
           float* __restrict__ out, int B, int E)
{
    __shared__ __align__(16) PairSmem psm[NPAIR];

    const int t = threadIdx.x;
    const int pair = t / NTP;
    const int td = t - pair * NTP;
    const int lane = td & 31, w = td >> 5;
    const int h = 2*w + (lane >> 4), cc = lane & 15;
    const int barid = pair + 1;

    PairSmem* ps = &psm[pair];

    const int pidx = blockIdx.x * NPAIR + pair;
    const int gg0 = 2*pidx;
    if (gg0 >= B) return;
    const int gg1 = (gg0 + 1 < B) ? gg0 + 1 : gg0;
    const int NE = E + NN;
    const int is64 = g_is64;
    const int gmine = w ? gg1 : gg0;   // graph this warp sorts

    if (lane < NN) ps->cnt[w][lane] = 0;

    // load + interleave features of both graphs (both warps cooperate)
    {
        const float4* xg0 = (const float4*)(feature + (size_t)gg0 * NN * FIN);
        const float4* xg1 = (const float4*)(feature + (size_t)gg1 * NN * FIN);
        ulonglong2* xo = (ulonglong2*)ps->xs2;
        for (int i = td; i < NN*FIN/4; i += NTP) {
            int n = i >> 5, k4 = i & 31;
            float4 a0 = xg0[n*32 + k4];
            float4 a1 = xg1[n*32 + k4];
            ulonglong2 v0, v1;
            v0.x = pk2(a0.x, a1.x); v0.y = pk2(a0.y, a1.y);
            v1.x = pk2(a0.z, a1.z); v1.y = pk2(a0.w, a1.w);
            xo[n*65 + 2*k4]     = v0;
            xo[n*65 + 2*k4 + 1] = v1;
        }
    }
    __syncwarp();

    // ---- warp-local counting sort: warp w sorts graph gmine into slot w ----
    for (int e = lane; e < NE; e += 32) {
        int d;
        if (e < E) {
            size_t base = ((size_t)gmine * E + e) * 2;
            d = is64 ? (int)((const long long*)eraw)[base + 1] : eraw[base + 1];
        } else d = e - E;
        atomicAdd(&ps->cnt[w][d], 1);
    }
    __syncwarp();
    if (lane == 0) {
        int s = 0;
        #pragma unroll
        for (int i = 0; i < NN; i++) {
            ps->off[w][i] = s; s += ps->cnt[w][i]; ps->cnt[w][i] = ps->off[w][i];
        }
        ps->off[w][NN] = s;
    }
    __syncwarp();
    for (int e = lane; e < NE; e += 32) {
        int s, d;
        if (e < E) {
            size_t base = ((size_t)gmine * E + e) * 2;
            if (is64) { const long long* p = (const long long*)eraw;
                        s = (int)p[base]; d = (int)p[base + 1]; }
            else      { s = eraw[base];   d = eraw[base + 1]; }
        } else { s = d = e - E; }
        int pos = atomicAdd(&ps->cnt[w][d], 1);
        ps->srcS[w][pos] = (unsigned char)s;
    }
    barp(barid);   // features + both graphs' srcS/off visible pair-wide

    gat_layer<FIN, 65, true >(g_W1q, as1, ad1, b1v, ps, td, lane, w, h, cc, barid);
    gat_layer<NC,  33, false>(g_W2q, as2, ad2, b2v, ps, td, lane, w, h, cc, barid);

    // ---- fused head: both graphs at once ----
    ull pp = 0ull;
    for (int i = td; i < NN*NC; i += NTP) {
        int n = i >> 6, c = i & 63;
        float wv = g_wfused[i];
        pp = fma2(ps->xs2[n*66 + c], pk2(wv, wv), pp);
    }
    float px, py; upk2(pp, px, py);
    #pragma unroll
    for (int o = 16; o; o >>= 1) {
        px += __shfl_xor_sync(0xffffffffu, px, o);
        py += __shfl_xor_sync(0xffffffffu, py, o);
    }
    if (lane == 0) ps->red[w] = make_float2(px, py);
    barp(barid);
    if (td == 0) {
        float sx = g_bfused + ps->red[0].x + ps->red[1].x;
        float sy = g_bfused + ps->red[0].y + ps->red[1].y;
        out[gg0] = 1.f / (1.f + __expf(-sx));
        out[gg1] = 1.f / (1.f + __expf(-sy));
    }
}

extern "C" void kernel_launch(void* const* d_in, const int* in_sizes, int n_in,
                              void* d_out, int out_size)
{
    const float* feature = (const float*)d_in[0];
    const int*   edges   = (const int*)  d_in[1];
    const float* W1   = (const float*)d_in[2];
    const float* as1  = (const float*)d_in[3];
    const float* ad1  = (const float*)d_in[4];
    const float* b1   = (const float*)d_in[5];
    const float* W2   = (const float*)d_in[6];
    const float* as2  = (const float*)d_in[7];
    const float* ad2  = (const float*)d_in[8];
    const float* b2   = (const float*)d_in[9];
    const float* Wlin = (const float*)d_in[10];
    const float* blin = (const float*)d_in[11];
    const float* Wpred= (const float*)d_in[12];
    const float* bpred= (const float*)d_in[13];

    int B = in_sizes[0] / (NN * FIN);       // 16384
    int E = in_sizes[1] / (2 * B);          // 182

    prep_kernel<<<48, 256>>>(W1, W2, Wlin, blin, Wpred, bpred, edges);
    int nPairs = (B + 1) / 2;
    int grid = (nPairs + NPAIR - 1) / NPAIR;
    gat_kernel<<<grid, NT>>>(feature, edges, as1, ad1, b1,
                             as2, ad2, b2, (float*)d_out, B, E);
}